// round 2
// baseline (speedup 1.0000x reference)
#include <cuda_runtime.h>
#include <math.h>

#define NN 50000
#define EE 500000
#define ET (EE + NN)
#define GG 64
#define SCAL 96
#define DD 32
#define INDIM 256
#define CC 128
#define H1N 4
#define NCLS 5

// ---------------- scratch (device globals; no allocation allowed) ----------
__device__ float g_feats[NN * INDIM];     // [N,256]
__device__ float g_h1[NN * H1N * CC];     // [N,512]
__device__ float g_out1[NN * H1N * CC];   // [N,512]
__device__ float g_h2[NN * CC];           // [N,128]
__device__ float g_out2[NN * CC];         // [N,128]
__device__ float g_asrc1[NN * H1N];
__device__ float g_adst1[NN * H1N];
__device__ float g_m1[NN * H1N];
__device__ float g_den1[NN * H1N];
__device__ float g_asrc2[NN];
__device__ float g_adst2[NN];
__device__ float g_m2[NN];
__device__ float g_den2[NN];
__device__ float g_pooled[GG * CC];

// ---------------- helpers ---------------------------------------------------
__device__ __forceinline__ void atomicMaxF(float* addr, float val) {
    int* ia = (int*)addr;
    int old = *ia;
    while (__int_as_float(old) < val) {
        int assumed = old;
        old = atomicCAS(ia, assumed, __float_as_int(val));
        if (old == assumed) break;
    }
}

// ---------------- init ------------------------------------------------------
__global__ void k_init() {
    int i = blockIdx.x * blockDim.x + threadIdx.x;
    int stride = gridDim.x * blockDim.x;
    for (int j = i; j < NN * H1N * CC; j += stride) g_out1[j] = 0.f;
    for (int j = i; j < NN * CC; j += stride) g_out2[j] = 0.f;
    for (int j = i; j < NN * H1N; j += stride) { g_m1[j] = -1e30f; g_den1[j] = 0.f; }
    for (int j = i; j < NN; j += stride) { g_m2[j] = -1e30f; g_den2[j] = 0.f; }
    for (int j = i; j < GG * CC; j += stride) g_pooled[j] = -1e30f;
}

// ---------------- feature build + layernorm ---------------------------------
__global__ void k_feats(const float* __restrict__ xs,
                        const int* __restrict__ xop, const int* __restrict__ xsrc,
                        const int* __restrict__ xsink, const int* __restrict__ xstr,
                        const int* __restrict__ xpay,
                        const float* __restrict__ eop, const float* __restrict__ esrc,
                        const float* __restrict__ esink, const float* __restrict__ estr,
                        const float* __restrict__ epay,
                        const float* __restrict__ ln_g, const float* __restrict__ ln_b) {
    int n = blockIdx.x;
    int t = threadIdx.x;  // 256 threads
    float v;
    if (t < SCAL) {
        v = xs[n * SCAL + t];
    } else {
        int grp = (t - SCAL) / DD;
        int d = (t - SCAL) % DD;
        const int* idxp; const float* tab; int L;
        switch (grp) {
            case 0: idxp = xop + n * 16; tab = eop; L = 16; break;
            case 1: idxp = xsrc + n * 8; tab = esrc; L = 8; break;
            case 2: idxp = xsink + n * 8; tab = esink; L = 8; break;
            case 3: idxp = xstr + n * 8; tab = estr; L = 8; break;
            default: idxp = xpay + n * 8; tab = epay; L = 8; break;
        }
        float s = 0.f, cnt = 0.f;
        for (int l = 0; l < L; l++) {
            int id = idxp[l];
            if (id != 0) { s += tab[id * DD + d]; cnt += 1.f; }
        }
        v = s / (cnt + 1e-9f);
    }
    __shared__ float sh[256];
    sh[t] = v;
    __syncthreads();
    for (int o = 128; o > 0; o >>= 1) { if (t < o) sh[t] += sh[t + o]; __syncthreads(); }
    float mu = sh[0] / 256.f;
    __syncthreads();
    float dv = v - mu;
    sh[t] = dv * dv;
    __syncthreads();
    for (int o = 128; o > 0; o >>= 1) { if (t < o) sh[t] += sh[t + o]; __syncthreads(); }
    float var = sh[0] / 256.f;
    g_feats[n * INDIM + t] = dv * rsqrtf(var + 1e-5f) * ln_g[t] + ln_b[t];
}

// ---------------- tiled SGEMM: C[M,N] = A[M,K] @ B[K,N] ---------------------
// BM=64 BN=64 BK=16, 256 threads, 4x4 per thread. K%16==0, N%64==0 assumed.
__global__ void k_sgemm(const float* __restrict__ A, const float* __restrict__ B,
                        float* __restrict__ Cmat, int M, int N, int K) {
    const int BM = 64, BN = 64, BK = 16, TM = 4, TN = 4;
    __shared__ float As[BK][BM];
    __shared__ float Bs[BK][BN];
    int block_row = blockIdx.y * BM, block_col = blockIdx.x * BN;
    int tid = threadIdx.x;
    int tr = tid / (BN / TN);  // 0..15
    int tc = tid % (BN / TN);  // 0..15
    float acc[TM][TN] = {};
    for (int k0 = 0; k0 < K; k0 += BK) {
        for (int i = tid; i < BM * BK; i += 256) {
            int m = i / BK, k = i % BK;
            int gm = block_row + m;
            As[k][m] = (gm < M) ? A[(size_t)gm * K + k0 + k] : 0.f;
        }
        for (int i = tid; i < BK * BN; i += 256) {
            int k = i / BN, nn = i % BN;
            Bs[k][nn] = B[(size_t)(k0 + k) * N + block_col + nn];
        }
        __syncthreads();
#pragma unroll
        for (int k = 0; k < BK; k++) {
            float a[TM], b[TN];
#pragma unroll
            for (int i = 0; i < TM; i++) a[i] = As[k][tr * TM + i];
#pragma unroll
            for (int j = 0; j < TN; j++) b[j] = Bs[k][tc * TN + j];
#pragma unroll
            for (int i = 0; i < TM; i++)
#pragma unroll
                for (int j = 0; j < TN; j++) acc[i][j] += a[i] * b[j];
        }
        __syncthreads();
    }
#pragma unroll
    for (int i = 0; i < TM; i++) {
        int gm = block_row + tr * TM + i;
        if (gm < M)
#pragma unroll
            for (int j = 0; j < TN; j++)
                Cmat[(size_t)gm * N + block_col + tc * TN + j] = acc[i][j];
    }
}

// ---------------- attention logits ------------------------------------------
__global__ void k_att1(const float* __restrict__ att_src, const float* __restrict__ att_dst) {
    int n = blockIdx.x;
    int w = threadIdx.x / 32;   // head
    int lane = threadIdx.x % 32;
    const float* hrow = g_h1 + (size_t)n * 512 + w * 128;
    float s1 = 0.f, s2 = 0.f;
    for (int c = lane; c < 128; c += 32) {
        float hv = hrow[c];
        s1 += hv * att_src[w * 128 + c];
        s2 += hv * att_dst[w * 128 + c];
    }
    for (int o = 16; o; o >>= 1) {
        s1 += __shfl_down_sync(0xffffffffu, s1, o);
        s2 += __shfl_down_sync(0xffffffffu, s2, o);
    }
    if (lane == 0) { g_asrc1[n * 4 + w] = s1; g_adst1[n * 4 + w] = s2; }
}

__global__ void k_att2(const float* __restrict__ att_src, const float* __restrict__ att_dst) {
    int n = blockIdx.x;
    int lane = threadIdx.x;
    const float* hrow = g_h2 + (size_t)n * 128;
    float s1 = 0.f, s2 = 0.f;
    for (int c = lane; c < 128; c += 32) {
        float hv = hrow[c];
        s1 += hv * att_src[c];
        s2 += hv * att_dst[c];
    }
    for (int o = 16; o; o >>= 1) {
        s1 += __shfl_down_sync(0xffffffffu, s1, o);
        s2 += __shfl_down_sync(0xffffffffu, s2, o);
    }
    if (lane == 0) { g_asrc2[n] = s1; g_adst2[n] = s2; }
}

// ---------------- edge passes: conv1 (4 heads) -------------------------------
__global__ void k_emax1(const int* __restrict__ ei) {
    int e = blockIdx.x * blockDim.x + threadIdx.x;
    if (e >= ET) return;
    int s, d;
    if (e < EE) { s = ei[e]; d = ei[EE + e]; } else { s = d = e - EE; }
#pragma unroll
    for (int h = 0; h < 4; h++) {
        float x = g_asrc1[s * 4 + h] + g_adst1[d * 4 + h];
        x = x > 0.f ? x : 0.2f * x;
        atomicMaxF(&g_m1[d * 4 + h], x);
    }
}

__global__ void k_esum1(const int* __restrict__ ei) {
    int e = blockIdx.x * blockDim.x + threadIdx.x;
    if (e >= ET) return;
    int s, d;
    if (e < EE) { s = ei[e]; d = ei[EE + e]; } else { s = d = e - EE; }
#pragma unroll
    for (int h = 0; h < 4; h++) {
        float x = g_asrc1[s * 4 + h] + g_adst1[d * 4 + h];
        x = x > 0.f ? x : 0.2f * x;
        atomicAdd(&g_den1[d * 4 + h], __expf(x - g_m1[d * 4 + h]));
    }
}

__global__ void k_emsg1(const int* __restrict__ ei) {
    int gw = (blockIdx.x * blockDim.x + threadIdx.x) / 32;
    int lane = threadIdx.x % 32;
    if (gw >= ET) return;
    int s, d;
    if (gw < EE) { s = ei[gw]; d = ei[EE + gw]; } else { s = d = gw - EE; }
    float alpha[4];
#pragma unroll
    for (int h = 0; h < 4; h++) {
        float x = g_asrc1[s * 4 + h] + g_adst1[d * 4 + h];
        x = x > 0.f ? x : 0.2f * x;
        alpha[h] = __expf(x - g_m1[d * 4 + h]) / (g_den1[d * 4 + h] + 1e-16f);
    }
    const float* hs = g_h1 + (size_t)s * 512;
    float* od = g_out1 + (size_t)d * 512;
#pragma unroll
    for (int h = 0; h < 4; h++)
#pragma unroll
        for (int k = 0; k < 4; k++) {
            int c = h * 128 + k * 32 + lane;
            atomicAdd(&od[c], hs[c] * alpha[h]);
        }
}

__global__ void k_fin1(const float* __restrict__ b1) {
    int i = blockIdx.x * blockDim.x + threadIdx.x;
    if (i >= NN * 512) return;
    int c = i % 512;
    float v = g_out1[i] + b1[c];
    g_out1[i] = v > 0.f ? v : expm1f(v);
}

// ---------------- edge passes: conv2 (1 head) --------------------------------
__global__ void k_emax2(const int* __restrict__ ei) {
    int e = blockIdx.x * blockDim.x + threadIdx.x;
    if (e >= ET) return;
    int s, d;
    if (e < EE) { s = ei[e]; d = ei[EE + e]; } else { s = d = e - EE; }
    float x = g_asrc2[s] + g_adst2[d];
    x = x > 0.f ? x : 0.2f * x;
    atomicMaxF(&g_m2[d], x);
}

__global__ void k_esum2(const int* __restrict__ ei) {
    int e = blockIdx.x * blockDim.x + threadIdx.x;
    if (e >= ET) return;
    int s, d;
    if (e < EE) { s = ei[e]; d = ei[EE + e]; } else { s = d = e - EE; }
    float x = g_asrc2[s] + g_adst2[d];
    x = x > 0.f ? x : 0.2f * x;
    atomicAdd(&g_den2[d], __expf(x - g_m2[d]));
}

__global__ void k_emsg2(const int* __restrict__ ei) {
    int gw = (blockIdx.x * blockDim.x + threadIdx.x) / 32;
    int lane = threadIdx.x % 32;
    if (gw >= ET) return;
    int s, d;
    if (gw < EE) { s = ei[gw]; d = ei[EE + gw]; } else { s = d = gw - EE; }
    float x = g_asrc2[s] + g_adst2[d];
    x = x > 0.f ? x : 0.2f * x;
    float alpha = __expf(x - g_m2[d]) / (g_den2[d] + 1e-16f);
    const float* hs = g_h2 + (size_t)s * 128;
    float* od = g_out2 + (size_t)d * 128;
#pragma unroll
    for (int k = 0; k < 4; k++) {
        int c = k * 32 + lane;
        atomicAdd(&od[c], hs[c] * alpha);
    }
}

__global__ void k_fin2(const float* __restrict__ b2) {
    int i = blockIdx.x * blockDim.x + threadIdx.x;
    if (i >= NN * 128) return;
    int c = i % 128;
    float v = g_out2[i] + b2[c];
    g_out2[i] = v > 0.f ? v : expm1f(v);
}

// ---------------- global max pool --------------------------------------------
__global__ void k_pool(const int* __restrict__ batch) {
    int i = blockIdx.x * blockDim.x + threadIdx.x;
    if (i >= NN * 128) return;
    int n = i / 128, c = i % 128;
    atomicMaxF(&g_pooled[batch[n] * 128 + c], g_out2[i]);
}

// ---------------- classifier --------------------------------------------------
__global__ void k_cls(const float* __restrict__ Wc1, const float* __restrict__ bc1,
                      const float* __restrict__ Wc2, const float* __restrict__ bc2,
                      float* __restrict__ out) {
    int g = blockIdx.x;
    int t = threadIdx.x;  // 64
    __shared__ float sp[128];
    __shared__ float sh[64];
    sp[t] = g_pooled[g * 128 + t];
    sp[t + 64] = g_pooled[g * 128 + 64 + t];
    __syncthreads();
    float s = bc1[t];
    for (int k = 0; k < 128; k++) s += sp[k] * Wc1[k * 64 + t];
    sh[t] = fmaxf(s, 0.f);
    __syncthreads();
    if (t < NCLS) {
        float o = bc2[t];
        for (int k = 0; k < 64; k++) o += sh[k] * Wc2[k * NCLS + t];
        out[g * NCLS + t] = o;
    }
}

// ---------------- launch ------------------------------------------------------
extern "C" void kernel_launch(void* const* d_in, const int* in_sizes, int n_in,
                              void* d_out, int out_size) {
    const float* xs    = (const float*)d_in[0];
    const int*   xop   = (const int*)d_in[1];
    const int*   xsrc  = (const int*)d_in[2];
    const int*   xsink = (const int*)d_in[3];
    const int*   xstr  = (const int*)d_in[4];
    const int*   xpay  = (const int*)d_in[5];
    const int*   ei    = (const int*)d_in[6];
    const int*   batch = (const int*)d_in[7];
    const float* eop   = (const float*)d_in[8];
    const float* esrc  = (const float*)d_in[9];
    const float* esink = (const float*)d_in[10];
    const float* estr  = (const float*)d_in[11];
    const float* epay  = (const float*)d_in[12];
    const float* ln_g  = (const float*)d_in[13];
    const float* ln_b  = (const float*)d_in[14];
    const float* W1    = (const float*)d_in[15];
    const float* as1   = (const float*)d_in[16];
    const float* ad1   = (const float*)d_in[17];
    const float* b1    = (const float*)d_in[18];
    const float* W2    = (const float*)d_in[19];
    const float* as2   = (const float*)d_in[20];
    const float* ad2   = (const float*)d_in[21];
    const float* b2    = (const float*)d_in[22];
    const float* Wc1   = (const float*)d_in[23];
    const float* bc1   = (const float*)d_in[24];
    const float* Wc2   = (const float*)d_in[25];
    const float* bc2   = (const float*)d_in[26];
    float* out = (float*)d_out;

    float *p_feats, *p_h1, *p_out1, *p_h2;
    cudaGetSymbolAddress((void**)&p_feats, g_feats);
    cudaGetSymbolAddress((void**)&p_h1, g_h1);
    cudaGetSymbolAddress((void**)&p_out1, g_out1);
    cudaGetSymbolAddress((void**)&p_h2, g_h2);

    k_init<<<2048, 256>>>();
    k_feats<<<NN, 256>>>(xs, xop, xsrc, xsink, xstr, xpay,
                         eop, esrc, esink, estr, epay, ln_g, ln_b);

    // GEMM1: [N,256] @ [256,512] -> [N,512]
    {
        dim3 grid(512 / 64, (NN + 63) / 64);
        k_sgemm<<<grid, 256>>>(p_feats, W1, p_h1, NN, 512, 256);
    }
    k_att1<<<NN, 128>>>(as1, ad1);

    int eb = (ET + 255) / 256;
    k_emax1<<<eb, 256>>>(ei);
    k_esum1<<<eb, 256>>>(ei);
    k_emsg1<<<(ET * 32 + 255) / 256, 256>>>(ei);
    k_fin1<<<(NN * 512 + 255) / 256, 256>>>(b1);

    // GEMM2: [N,512] @ [512,128] -> [N,128]
    {
        dim3 grid(128 / 64, (NN + 63) / 64);
        k_sgemm<<<grid, 256>>>(p_out1, W2, p_h2, NN, 128, 512);
    }
    k_att2<<<NN, 32>>>(as2, ad2);

    k_emax2<<<eb, 256>>>(ei);
    k_esum2<<<eb, 256>>>(ei);
    k_emsg2<<<(ET * 32 + 255) / 256, 256>>>(ei);
    k_fin2<<<(NN * 128 + 255) / 256, 256>>>(b2);

    k_pool<<<(NN * 128 + 255) / 256, 256>>>(batch);
    k_cls<<<GG, 64>>>(Wc1, bc1, Wc2, bc2, out);
}

// round 4
// speedup vs baseline: 3.0081x; 3.0081x over previous
#include <cuda_runtime.h>
#include <math.h>
#include <stdint.h>

#define NN 50000
#define EE 500000
#define ET (EE + NN)
#define GG 64
#define SCAL 96
#define DD 32
#define INDIM 256
#define CC 128
#define H1N 4
#define NCLS 5

// ---------------- scratch (device globals; no allocation allowed) ----------
__device__ float g_feats[NN * INDIM];     // [N,256]
__device__ float g_h1[NN * H1N * CC];     // [N,512]
__device__ float g_out1[NN * H1N * CC];   // [N,512]
__device__ float g_h2[NN * CC];           // [N,128]
__device__ float g_out2[NN * CC];         // [N,128]
__device__ float g_asrc1[NN * H1N];
__device__ float g_adst1[NN * H1N];
__device__ float g_asrc2[NN];
__device__ float g_adst2[NN];
__device__ float g_pooled[GG * CC];
__device__ float g_P1[INDIM * 8];         // [k][j]  j = h*2 + (0:src,1:dst)
// CSR scratch
__device__ int g_deg[NN];
__device__ int g_rowptr[NN + 1];
__device__ int g_cursor[NN];
__device__ int g_csrc[ET];

// ---------------- CSR build -------------------------------------------------
__global__ void k_zero_deg() {
    int i = blockIdx.x * blockDim.x + threadIdx.x;
    if (i < NN) g_deg[i] = 0;
}

__global__ void k_deg(const int* __restrict__ ei) {
    int e = blockIdx.x * blockDim.x + threadIdx.x;
    if (e >= ET) return;
    int d = (e < EE) ? ei[EE + e] : (e - EE);
    atomicAdd(&g_deg[d], 1);
}

__global__ void k_scan() {
    __shared__ int sh[1024];
    int t = threadIdx.x;
    const int CH = 49;  // 1024*49 >= 50000
    int start = t * CH;
    int s = 0;
    for (int i = start; i < start + CH && i < NN; i++) s += g_deg[i];
    sh[t] = s;
    __syncthreads();
    for (int o = 1; o < 1024; o <<= 1) {
        int v = (t >= o) ? sh[t - o] : 0;
        __syncthreads();
        sh[t] += v;
        __syncthreads();
    }
    int run = sh[t] - s;  // exclusive prefix of this chunk
    for (int i = start; i < start + CH && i < NN; i++) {
        g_rowptr[i] = run;
        g_cursor[i] = run;
        run += g_deg[i];
    }
    if (t == 1023) g_rowptr[NN] = sh[1023];
}

__global__ void k_fill(const int* __restrict__ ei) {
    int e = blockIdx.x * blockDim.x + threadIdx.x;
    if (e >= ET) return;
    int s, d;
    if (e < EE) { s = ei[e]; d = ei[EE + e]; } else { s = d = e - EE; }
    int pos = atomicAdd(&g_cursor[d], 1);
    g_csrc[pos] = s;
}

// ---------------- feature build + layernorm ---------------------------------
__global__ void k_feats(const float* __restrict__ xs,
                        const int* __restrict__ xop, const int* __restrict__ xsrc,
                        const int* __restrict__ xsink, const int* __restrict__ xstr,
                        const int* __restrict__ xpay,
                        const float* __restrict__ eop, const float* __restrict__ esrc,
                        const float* __restrict__ esink, const float* __restrict__ estr,
                        const float* __restrict__ epay,
                        const float* __restrict__ ln_g, const float* __restrict__ ln_b) {
    int n = blockIdx.x;
    int t = threadIdx.x;  // 256 threads
    float v;
    if (t < SCAL) {
        v = xs[n * SCAL + t];
    } else {
        int grp = (t - SCAL) / DD;
        int d = (t - SCAL) % DD;
        const int* idxp; const float* tab; int L;
        switch (grp) {
            case 0: idxp = xop + n * 16; tab = eop; L = 16; break;
            case 1: idxp = xsrc + n * 8; tab = esrc; L = 8; break;
            case 2: idxp = xsink + n * 8; tab = esink; L = 8; break;
            case 3: idxp = xstr + n * 8; tab = estr; L = 8; break;
            default: idxp = xpay + n * 8; tab = epay; L = 8; break;
        }
        float s = 0.f, cnt = 0.f;
        for (int l = 0; l < L; l++) {
            int id = idxp[l];
            if (id != 0) { s += tab[id * DD + d]; cnt += 1.f; }
        }
        v = s / (cnt + 1e-9f);
    }
    __shared__ float sh[256];
    sh[t] = v;
    __syncthreads();
    for (int o = 128; o > 0; o >>= 1) { if (t < o) sh[t] += sh[t + o]; __syncthreads(); }
    float mu = sh[0] / 256.f;
    __syncthreads();
    float dv = v - mu;
    sh[t] = dv * dv;
    __syncthreads();
    for (int o = 128; o > 0; o >>= 1) { if (t < o) sh[t] += sh[t + o]; __syncthreads(); }
    float var = sh[0] / 256.f;
    g_feats[n * INDIM + t] = dv * rsqrtf(var + 1e-5f) * ln_g[t] + ln_b[t];
}

// ---------------- TF32 tensor-core GEMM: C[M,N]=A[M,K]@B[K,N] ---------------
// BM=128 BN=128 BK=32, 256 threads = 8 warps (4x2), warp tile 32x64.
#define MMA_TF32(d0,d1,d2,d3,a0,a1,a2,a3,b0,b1) \
    asm volatile("mma.sync.aligned.m16n8k8.row.col.f32.tf32.tf32.f32 " \
                 "{%0,%1,%2,%3},{%4,%5,%6,%7},{%8,%9},{%0,%1,%2,%3};" \
                 : "+f"(d0), "+f"(d1), "+f"(d2), "+f"(d3) \
                 : "r"(a0), "r"(a1), "r"(a2), "r"(a3), "r"(b0), "r"(b1))

__device__ __forceinline__ uint32_t f2tf32(float f) {
    uint32_t u;
    asm("cvt.rna.tf32.f32 %0, %1;" : "=r"(u) : "f"(f));
    return u;
}

__global__ void __launch_bounds__(256) k_mma(const float* __restrict__ A,
                                             const float* __restrict__ B,
                                             float* __restrict__ C, int M, int N, int K) {
    __shared__ uint32_t As[128][36];   // [m][k], pitch 36 -> frag loads conflict-free
    __shared__ uint32_t Bs[32][136];   // [k][n], pitch 136 -> frag loads conflict-free
    int tid = threadIdx.x;
    int wid = tid >> 5, lane = tid & 31;
    int wm = (wid & 3) * 32;
    int wn = (wid >> 2) * 64;
    int gid = lane >> 2, tig = lane & 3;
    int row0 = blockIdx.y * 128, col0 = blockIdx.x * 128;
    float acc[2][8][4];
#pragma unroll
    for (int i = 0; i < 2; i++)
#pragma unroll
        for (int j = 0; j < 8; j++)
#pragma unroll
            for (int q = 0; q < 4; q++) acc[i][j][q] = 0.f;

    for (int k0 = 0; k0 < K; k0 += 32) {
#pragma unroll
        for (int r = 0; r < 4; r++) {
            int u = tid + 256 * r;
            int m = u >> 3, kg = (u & 7) * 4;
            float4 v = make_float4(0.f, 0.f, 0.f, 0.f);
            int gm = row0 + m;
            if (gm < M) v = *(const float4*)(A + (size_t)gm * K + k0 + kg);
            uint4 t;
            t.x = f2tf32(v.x); t.y = f2tf32(v.y); t.z = f2tf32(v.z); t.w = f2tf32(v.w);
            *(uint4*)(&As[m][kg]) = t;
        }
#pragma unroll
        for (int r = 0; r < 4; r++) {
            int u = tid + 256 * r;
            int kk = u >> 5, ng = (u & 31) * 4;
            float4 v = *(const float4*)(B + (size_t)(k0 + kk) * N + col0 + ng);
            uint4 t;
            t.x = f2tf32(v.x); t.y = f2tf32(v.y); t.z = f2tf32(v.z); t.w = f2tf32(v.w);
            *(uint4*)(&Bs[kk][ng]) = t;
        }
        __syncthreads();
#pragma unroll
        for (int ks = 0; ks < 4; ks++) {
            int kk = ks * 8;
            uint32_t a[2][4];
#pragma unroll
            for (int mi = 0; mi < 2; mi++) {
                int r = wm + mi * 16 + gid;
                a[mi][0] = As[r][kk + tig];
                a[mi][1] = As[r + 8][kk + tig];
                a[mi][2] = As[r][kk + tig + 4];
                a[mi][3] = As[r + 8][kk + tig + 4];
            }
#pragma unroll
            for (int ni = 0; ni < 8; ni++) {
                uint32_t b0 = Bs[kk + tig][wn + ni * 8 + gid];
                uint32_t b1 = Bs[kk + tig + 4][wn + ni * 8 + gid];
#pragma unroll
                for (int mi = 0; mi < 2; mi++) {
                    MMA_TF32(acc[mi][ni][0], acc[mi][ni][1], acc[mi][ni][2], acc[mi][ni][3],
                             a[mi][0], a[mi][1], a[mi][2], a[mi][3], b0, b1);
                }
            }
        }
        __syncthreads();
    }
#pragma unroll
    for (int mi = 0; mi < 2; mi++) {
#pragma unroll
        for (int ni = 0; ni < 8; ni++) {
            int r = row0 + wm + mi * 16 + gid;
            int c = col0 + wn + ni * 8 + tig * 2;
            if (r < M)
                *(float2*)(C + (size_t)r * N + c) = make_float2(acc[mi][ni][0], acc[mi][ni][1]);
            if (r + 8 < M)
                *(float2*)(C + (size_t)(r + 8) * N + c) = make_float2(acc[mi][ni][2], acc[mi][ni][3]);
        }
    }
}

// ---------------- attention logits (linear trick for conv1) ------------------
__global__ void k_prep1(const float* __restrict__ W1, const float* __restrict__ as1,
                        const float* __restrict__ ad1) {
    int idx = blockIdx.x * 256 + threadIdx.x;  // 2048
    if (idx >= 2048) return;
    int kk = idx >> 3, j = idx & 7, h = j >> 1;
    const float* av = (j & 1) ? ad1 : as1;
    float s = 0.f;
    for (int c = 0; c < 128; c++) s += W1[kk * 512 + h * 128 + c] * av[h * 128 + c];
    g_P1[kk * 8 + j] = s;
}

__global__ void k_attlin1() {
    __shared__ float Psh[8][256];
    int t = threadIdx.x;
    for (int i = t; i < 2048; i += 256) Psh[i & 7][i >> 3] = g_P1[i];
    __syncthreads();
    int n = blockIdx.x * 8 + (t >> 5);
    if (n >= NN) return;
    int lane = t & 31;
    const float* f = g_feats + (size_t)n * 256;
    float acc[8];
#pragma unroll
    for (int j = 0; j < 8; j++) acc[j] = 0.f;
    for (int k = lane; k < 256; k += 32) {
        float fv = f[k];
#pragma unroll
        for (int j = 0; j < 8; j++) acc[j] += fv * Psh[j][k];
    }
#pragma unroll
    for (int j = 0; j < 8; j++)
        for (int o = 16; o; o >>= 1) acc[j] += __shfl_down_sync(0xffffffffu, acc[j], o);
    if (lane == 0) {
#pragma unroll
        for (int h = 0; h < 4; h++) {
            g_asrc1[n * 4 + h] = acc[h * 2];
            g_adst1[n * 4 + h] = acc[h * 2 + 1];
        }
    }
}

__global__ void k_att2(const float* __restrict__ as2, const float* __restrict__ ad2) {
    int n = blockIdx.x * 8 + (threadIdx.x >> 5);
    if (n >= NN) return;
    int lane = threadIdx.x & 31;
    const float* hrow = g_h2 + (size_t)n * 128;
    float s1 = 0.f, s2 = 0.f;
    for (int c = lane; c < 128; c += 32) {
        float hv = hrow[c];
        s1 += hv * as2[c];
        s2 += hv * ad2[c];
    }
    for (int o = 16; o; o >>= 1) {
        s1 += __shfl_down_sync(0xffffffffu, s1, o);
        s2 += __shfl_down_sync(0xffffffffu, s2, o);
    }
    if (lane == 0) { g_asrc2[n] = s1; g_adst2[n] = s2; }
}

// ---------------- fused CSR aggregation: conv1 (warp per node) ---------------
__global__ void k_agg1(const float* __restrict__ b1) {
    int node = blockIdx.x * 8 + (threadIdx.x >> 5);
    if (node >= NN) return;
    int lane = threadIdx.x & 31;
    int h = lane & 3;
    int beg = g_rowptr[node], end = g_rowptr[node + 1];
    float adst = g_adst1[node * 4 + h];
    // phase A: segment max per head (8 lane-groups x 4 heads)
    float mx = -1e30f;
    for (int i = beg + (lane >> 2); i < end; i += 8) {
        int s = g_csrc[i];
        float x = g_asrc1[s * 4 + h] + adst;
        x = x > 0.f ? x : 0.2f * x;
        mx = fmaxf(mx, x);
    }
    mx = fmaxf(mx, __shfl_xor_sync(0xffffffffu, mx, 4));
    mx = fmaxf(mx, __shfl_xor_sync(0xffffffffu, mx, 8));
    mx = fmaxf(mx, __shfl_xor_sync(0xffffffffu, mx, 16));
    // phase B: denom + weighted message accumulation
    float den = 0.f;
    float acc[16];
#pragma unroll
    for (int j = 0; j < 16; j++) acc[j] = 0.f;
    for (int i = beg; i < end; i++) {
        int s = g_csrc[i];
        float x = g_asrc1[s * 4 + h] + adst;
        x = x > 0.f ? x : 0.2f * x;
        float w = __expf(x - mx);
        den += w;
        float w0 = __shfl_sync(0xffffffffu, w, 0);
        float w1 = __shfl_sync(0xffffffffu, w, 1);
        float w2 = __shfl_sync(0xffffffffu, w, 2);
        float w3 = __shfl_sync(0xffffffffu, w, 3);
        const float* hs = g_h1 + (size_t)s * 512;
#pragma unroll
        for (int j = 0; j < 16; j++) {
            float wv = (j < 4) ? w0 : (j < 8) ? w1 : (j < 12) ? w2 : w3;
            acc[j] += wv * hs[j * 32 + lane];
        }
    }
    float* od = g_out1 + (size_t)node * 512;
#pragma unroll
    for (int j = 0; j < 16; j++) {
        float dh = __shfl_sync(0xffffffffu, den, j >> 2);
        float v = acc[j] / (dh + 1e-16f) + b1[j * 32 + lane];
        od[j * 32 + lane] = v > 0.f ? v : expm1f(v);
    }
}

// ---------------- fused CSR aggregation: conv2 (warp per node) ---------------
__global__ void k_agg2(const float* __restrict__ b2) {
    int node = blockIdx.x * 8 + (threadIdx.x >> 5);
    if (node >= NN) return;
    int lane = threadIdx.x & 31;
    int beg = g_rowptr[node], end = g_rowptr[node + 1];
    float adst = g_adst2[node];
    float mx = -1e30f;
    for (int i = beg + lane; i < end; i += 32) {
        int s = g_csrc[i];
        float x = g_asrc2[s] + adst;
        x = x > 0.f ? x : 0.2f * x;
        mx = fmaxf(mx, x);
    }
#pragma unroll
    for (int o = 16; o; o >>= 1) mx = fmaxf(mx, __shfl_xor_sync(0xffffffffu, mx, o));
    float den = 0.f;
    float acc[4] = {0.f, 0.f, 0.f, 0.f};
    for (int i = beg; i < end; i++) {
        int s = g_csrc[i];
        float x = g_asrc2[s] + adst;
        x = x > 0.f ? x : 0.2f * x;
        float w = __expf(x - mx);
        den += w;
        const float* hs = g_h2 + (size_t)s * 128;
#pragma unroll
        for (int j = 0; j < 4; j++) acc[j] += w * hs[j * 32 + lane];
    }
    float* od = g_out2 + (size_t)node * 128;
    float inv = 1.f / (den + 1e-16f);
#pragma unroll
    for (int j = 0; j < 4; j++) {
        float v = acc[j] * inv + b2[j * 32 + lane];
        od[j * 32 + lane] = v > 0.f ? v : expm1f(v);
    }
}

// ---------------- global max pool (block per graph, binary search) -----------
__global__ void k_pool(const int* __restrict__ batch) {
    int g = blockIdx.x, c = threadIdx.x;  // 128 threads
    int lo, hi;
    { int a = 0, b = NN; while (a < b) { int m = (a + b) >> 1; if (batch[m] < g) a = m + 1; else b = m; } lo = a; }
    { int a = lo, b = NN; while (a < b) { int m = (a + b) >> 1; if (batch[m] < g + 1) a = m + 1; else b = m; } hi = a; }
    float mx = -3.4e38f;
    for (int n = lo; n < hi; n++) mx = fmaxf(mx, g_out2[(size_t)n * 128 + c]);
    g_pooled[g * 128 + c] = mx;
}

// ---------------- classifier --------------------------------------------------
__global__ void k_cls(const float* __restrict__ Wc1, const float* __restrict__ bc1,
                      const float* __restrict__ Wc2, const float* __restrict__ bc2,
                      float* __restrict__ out) {
    int g = blockIdx.x;
    int t = threadIdx.x;  // 64
    __shared__ float sp[128];
    __shared__ float sh[64];
    sp[t] = g_pooled[g * 128 + t];
    sp[t + 64] = g_pooled[g * 128 + 64 + t];
    __syncthreads();
    float s = bc1[t];
    for (int k = 0; k < 128; k++) s += sp[k] * Wc1[k * 64 + t];
    sh[t] = fmaxf(s, 0.f);
    __syncthreads();
    if (t < NCLS) {
        float o = bc2[t];
        for (int k = 0; k < 64; k++) o += sh[k] * Wc2[k * NCLS + t];
        out[g * NCLS + t] = o;
    }
}

// ---------------- launch ------------------------------------------------------
extern "C" void kernel_launch(void* const* d_in, const int* in_sizes, int n_in,
                              void* d_out, int out_size) {
    const float* xs    = (const float*)d_in[0];
    const int*   xop   = (const int*)d_in[1];
    const int*   xsrc  = (const int*)d_in[2];
    const int*   xsink = (const int*)d_in[3];
    const int*   xstr  = (const int*)d_in[4];
    const int*   xpay  = (const int*)d_in[5];
    const int*   ei    = (const int*)d_in[6];
    const int*   batch = (const int*)d_in[7];
    const float* eop   = (const float*)d_in[8];
    const float* esrc  = (const float*)d_in[9];
    const float* esink = (const float*)d_in[10];
    const float* estr  = (const float*)d_in[11];
    const float* epay  = (const float*)d_in[12];
    const float* ln_g  = (const float*)d_in[13];
    const float* ln_b  = (const float*)d_in[14];
    const float* W1    = (const float*)d_in[15];
    const float* as1   = (const float*)d_in[16];
    const float* ad1   = (const float*)d_in[17];
    const float* b1    = (const float*)d_in[18];
    const float* W2    = (const float*)d_in[19];
    const float* as2   = (const float*)d_in[20];
    const float* ad2   = (const float*)d_in[21];
    const float* b2    = (const float*)d_in[22];
    const float* Wc1   = (const float*)d_in[23];
    const float* bc1   = (const float*)d_in[24];
    const float* Wc2   = (const float*)d_in[25];
    const float* bc2   = (const float*)d_in[26];
    float* out = (float*)d_out;

    float *p_feats, *p_h1, *p_out1, *p_h2;
    cudaGetSymbolAddress((void**)&p_feats, g_feats);
    cudaGetSymbolAddress((void**)&p_h1, g_h1);
    cudaGetSymbolAddress((void**)&p_out1, g_out1);
    cudaGetSymbolAddress((void**)&p_h2, g_h2);

    int eb = (ET + 255) / 256;
    int nwb = (NN + 7) / 8;  // warp-per-node blocks (256 thr)

    // CSR build
    k_zero_deg<<<(NN + 255) / 256, 256>>>();
    k_deg<<<eb, 256>>>(ei);
    k_scan<<<1, 1024>>>();
    k_fill<<<eb, 256>>>(ei);

    // features
    k_feats<<<NN, 256>>>(xs, xop, xsrc, xsink, xstr, xpay,
                         eop, esrc, esink, estr, epay, ln_g, ln_b);

    // conv1
    k_prep1<<<8, 256>>>(W1, as1, ad1);
    {
        dim3 grid(512 / 128, (NN + 127) / 128);
        k_mma<<<grid, 256>>>(p_feats, W1, p_h1, NN, 512, 256);
    }
    k_attlin1<<<nwb, 256>>>();
    k_agg1<<<nwb, 256>>>(b1);

    // conv2
    {
        dim3 grid(1, (NN + 127) / 128);
        k_mma<<<grid, 256>>>(p_out1, W2, p_h2, NN, 128, 512);
    }
    k_att2<<<nwb, 256>>>(as2, ad2);
    k_agg2<<<nwb, 256>>>(b2);

    // pool + classify
    k_pool<<<GG, 128>>>(batch);
    k_cls<<<GG, 64>>>(Wc1, bc1, Wc2, bc2, out);
}

// round 6
// speedup vs baseline: 3.2373x; 1.0762x over previous
#include <cuda_runtime.h>
#include <cuda_fp16.h>
#include <math.h>
#include <stdint.h>

#define NN 50000
#define EE 500000
#define ET (EE + NN)
#define GG 64
#define SCAL 96
#define DD 32
#define INDIM 256
#define CC 128
#define H1N 4
#define NCLS 5

// ---------------- scratch (device globals; no allocation allowed) ----------
__device__ float  g_feats[NN * INDIM];       // [N,256] fp32
__device__ __half g_h1h[NN * H1N * CC];      // [N,512] fp16
__device__ __half g_out1h[NN * H1N * CC];    // [N,512] fp16
__device__ __half g_h2h[NN * CC];            // [N,128] fp16
__device__ float  g_out2[NN * CC];           // [N,128] fp32 (feeds pool)
__device__ float  g_asrc1[NN * H1N];
__device__ float  g_adst1[NN * H1N];
__device__ float  g_asrc2[NN];
__device__ float  g_adst2[NN];
__device__ float  g_pooled[GG * CC];
__device__ float  g_P1[INDIM * 8];           // [k][j]  j = h*2 + (0:src,1:dst)
// CSR scratch
__device__ int g_deg[NN];
__device__ int g_rowptr[NN + 1];
__device__ int g_cursor[NN];
__device__ int g_csrc[ET];

// ---------------- CSR build -------------------------------------------------
__global__ void k_zero_deg() {
    int i = blockIdx.x * blockDim.x + threadIdx.x;
    if (i < NN) g_deg[i] = 0;
}

__global__ void k_deg(const int* __restrict__ ei) {
    int e = blockIdx.x * blockDim.x + threadIdx.x;
    if (e >= ET) return;
    int d = (e < EE) ? ei[EE + e] : (e - EE);
    atomicAdd(&g_deg[d], 1);
}

__global__ void k_scan() {
    __shared__ int sh[1024];
    int t = threadIdx.x;
    const int CH = 49;  // 1024*49 >= 50000
    int start = t * CH;
    int s = 0;
    for (int i = start; i < start + CH && i < NN; i++) s += g_deg[i];
    sh[t] = s;
    __syncthreads();
    for (int o = 1; o < 1024; o <<= 1) {
        int v = (t >= o) ? sh[t - o] : 0;
        __syncthreads();
        sh[t] += v;
        __syncthreads();
    }
    int run = sh[t] - s;  // exclusive prefix of this chunk
    for (int i = start; i < start + CH && i < NN; i++) {
        g_rowptr[i] = run;
        g_cursor[i] = run;
        run += g_deg[i];
    }
    if (t == 1023) g_rowptr[NN] = sh[1023];
}

__global__ void k_fill(const int* __restrict__ ei) {
    int e = blockIdx.x * blockDim.x + threadIdx.x;
    if (e >= ET) return;
    int s, d;
    if (e < EE) { s = ei[e]; d = ei[EE + e]; } else { s = d = e - EE; }
    int pos = atomicAdd(&g_cursor[d], 1);
    g_csrc[pos] = s;
}

// ---------------- attention projection prep (runs BEFORE k_feats) -----------
__global__ void k_prep1(const float* __restrict__ W1, const float* __restrict__ as1,
                        const float* __restrict__ ad1) {
    int idx = blockIdx.x * 256 + threadIdx.x;  // 2048
    if (idx >= 2048) return;
    int kk = idx >> 3, j = idx & 7, h = j >> 1;
    const float* av = (j & 1) ? ad1 : as1;
    float s = 0.f;
    for (int c = 0; c < 128; c++) s += W1[kk * 512 + h * 128 + c] * av[h * 128 + c];
    g_P1[kk * 8 + j] = s;
}

// ---------------- feature build + LN + fused conv1 attention logits ---------
__global__ void k_feats(const float* __restrict__ xs,
                        const int* __restrict__ xop, const int* __restrict__ xsrc,
                        const int* __restrict__ xsink, const int* __restrict__ xstr,
                        const int* __restrict__ xpay,
                        const float* __restrict__ eop, const float* __restrict__ esrc,
                        const float* __restrict__ esink, const float* __restrict__ estr,
                        const float* __restrict__ epay,
                        const float* __restrict__ ln_g, const float* __restrict__ ln_b) {
    int n = blockIdx.x;
    int t = threadIdx.x;  // 256 threads
    int w = t >> 5, lane = t & 31;
    float v;
    if (t < SCAL) {
        v = xs[n * SCAL + t];
    } else {
        int grp = (t - SCAL) / DD;
        int d = (t - SCAL) % DD;
        const int* idxp; const float* tab; int L;
        switch (grp) {
            case 0: idxp = xop + n * 16; tab = eop; L = 16; break;
            case 1: idxp = xsrc + n * 8; tab = esrc; L = 8; break;
            case 2: idxp = xsink + n * 8; tab = esink; L = 8; break;
            case 3: idxp = xstr + n * 8; tab = estr; L = 8; break;
            default: idxp = xpay + n * 8; tab = epay; L = 8; break;
        }
        float s = 0.f, cnt = 0.f;
        for (int l = 0; l < L; l++) {
            int id = idxp[l];
            if (id != 0) { s += tab[id * DD + d]; cnt += 1.f; }
        }
        v = s / (cnt + 1e-9f);
    }
    // single-pass LN stats: warp reduce sum & sumsq, one sync
    __shared__ float smA[8], smB[8];
    __shared__ float sm8[8][8];
    float s1 = v, s2 = v * v;
#pragma unroll
    for (int o = 16; o; o >>= 1) {
        s1 += __shfl_xor_sync(0xffffffffu, s1, o);
        s2 += __shfl_xor_sync(0xffffffffu, s2, o);
    }
    if (lane == 0) { smA[w] = s1; smB[w] = s2; }
    __syncthreads();
    float S = 0.f, S2 = 0.f;
#pragma unroll
    for (int i = 0; i < 8; i++) { S += smA[i]; S2 += smB[i]; }
    float mu = S * (1.f / 256.f);
    float var = S2 * (1.f / 256.f) - mu * mu;
    float o = (v - mu) * rsqrtf(var + 1e-5f) * ln_g[t] + ln_b[t];
    g_feats[n * INDIM + t] = o;
    // fused conv1 attention logits: acc_j = sum_k o_k * P1[k][j]
    float pj[8];
#pragma unroll
    for (int j = 0; j < 8; j++) pj[j] = o * g_P1[t * 8 + j];
#pragma unroll
    for (int j = 0; j < 8; j++)
#pragma unroll
        for (int off = 16; off; off >>= 1) pj[j] += __shfl_xor_sync(0xffffffffu, pj[j], off);
    if (lane == 0) {
#pragma unroll
        for (int j = 0; j < 8; j++) sm8[w][j] = pj[j];
    }
    __syncthreads();
    if (t < 8) {
        float s = 0.f;
#pragma unroll
        for (int i = 0; i < 8; i++) s += sm8[i][t];
        int h = t >> 1;
        if (t & 1) g_adst1[n * 4 + h] = s;
        else       g_asrc1[n * 4 + h] = s;
    }
}

// ---------------- TF32 tensor-core GEMM: C[M,N]=A[M,K]@B[K,N], C fp16 -------
#define MMA_TF32(d0,d1,d2,d3,a0,a1,a2,a3,b0,b1) \
    asm volatile("mma.sync.aligned.m16n8k8.row.col.f32.tf32.tf32.f32 " \
                 "{%0,%1,%2,%3},{%4,%5,%6,%7},{%8,%9},{%0,%1,%2,%3};" \
                 : "+f"(d0), "+f"(d1), "+f"(d2), "+f"(d3) \
                 : "r"(a0), "r"(a1), "r"(a2), "r"(a3), "r"(b0), "r"(b1))

__device__ __forceinline__ uint32_t f2tf32(float f) {
    uint32_t u;
    asm("cvt.rna.tf32.f32 %0, %1;" : "=r"(u) : "f"(f));
    return u;
}

__device__ __forceinline__ void loadA4(const float* p, float f[4]) {
    float4 v = *(const float4*)p;
    f[0] = v.x; f[1] = v.y; f[2] = v.z; f[3] = v.w;
}
__device__ __forceinline__ void loadA4(const __half* p, float f[4]) {
    const __half2* q = (const __half2*)p;
    float2 a = __half22float2(q[0]), b = __half22float2(q[1]);
    f[0] = a.x; f[1] = a.y; f[2] = b.x; f[3] = b.y;
}

template <typename TA>
__global__ void __launch_bounds__(256) k_mma(const TA* __restrict__ A,
                                             const float* __restrict__ B,
                                             __half* __restrict__ C, int M, int N, int K) {
    __shared__ uint32_t As[128][36];   // [m][k]
    __shared__ uint32_t Bs[32][136];   // [k][n]
    int tid = threadIdx.x;
    int wid = tid >> 5, lane = tid & 31;
    int wm = (wid & 3) * 32;
    int wn = (wid >> 2) * 64;
    int gid = lane >> 2, tig = lane & 3;
    int row0 = blockIdx.y * 128, col0 = blockIdx.x * 128;
    float acc[2][8][4];
#pragma unroll
    for (int i = 0; i < 2; i++)
#pragma unroll
        for (int j = 0; j < 8; j++)
#pragma unroll
            for (int q = 0; q < 4; q++) acc[i][j][q] = 0.f;

    for (int k0 = 0; k0 < K; k0 += 32) {
#pragma unroll
        for (int r = 0; r < 4; r++) {
            int u = tid + 256 * r;
            int m = u >> 3, kg = (u & 7) * 4;
            float f[4] = {0.f, 0.f, 0.f, 0.f};
            int gm = row0 + m;
            if (gm < M) loadA4(A + (size_t)gm * K + k0 + kg, f);
            uint4 tt;
            tt.x = f2tf32(f[0]); tt.y = f2tf32(f[1]); tt.z = f2tf32(f[2]); tt.w = f2tf32(f[3]);
            *(uint4*)(&As[m][kg]) = tt;
        }
#pragma unroll
        for (int r = 0; r < 4; r++) {
            int u = tid + 256 * r;
            int kk = u >> 5, ng = (u & 31) * 4;
            float4 v = *(const float4*)(B + (size_t)(k0 + kk) * N + col0 + ng);
            uint4 tt;
            tt.x = f2tf32(v.x); tt.y = f2tf32(v.y); tt.z = f2tf32(v.z); tt.w = f2tf32(v.w);
            *(uint4*)(&Bs[kk][ng]) = tt;
        }
        __syncthreads();
#pragma unroll
        for (int ks = 0; ks < 4; ks++) {
            int kk = ks * 8;
            uint32_t a[2][4];
#pragma unroll
            for (int mi = 0; mi < 2; mi++) {
                int r = wm + mi * 16 + gid;
                a[mi][0] = As[r][kk + tig];
                a[mi][1] = As[r + 8][kk + tig];
                a[mi][2] = As[r][kk + tig + 4];
                a[mi][3] = As[r + 8][kk + tig + 4];
            }
#pragma unroll
            for (int ni = 0; ni < 8; ni++) {
                uint32_t b0 = Bs[kk + tig][wn + ni * 8 + gid];
                uint32_t b1 = Bs[kk + tig + 4][wn + ni * 8 + gid];
#pragma unroll
                for (int mi = 0; mi < 2; mi++) {
                    MMA_TF32(acc[mi][ni][0], acc[mi][ni][1], acc[mi][ni][2], acc[mi][ni][3],
                             a[mi][0], a[mi][1], a[mi][2], a[mi][3], b0, b1);
                }
            }
        }
        __syncthreads();
    }
#pragma unroll
    for (int mi = 0; mi < 2; mi++) {
#pragma unroll
        for (int ni = 0; ni < 8; ni++) {
            int r = row0 + wm + mi * 16 + gid;
            int c = col0 + wn + ni * 8 + tig * 2;
            if (r < M)
                *(__half2*)(C + (size_t)r * N + c) = __floats2half2_rn(acc[mi][ni][0], acc[mi][ni][1]);
            if (r + 8 < M)
                *(__half2*)(C + (size_t)(r + 8) * N + c) = __floats2half2_rn(acc[mi][ni][2], acc[mi][ni][3]);
        }
    }
}

// ---------------- conv2 attention logits (reads fp16 h2) --------------------
__global__ void k_att2(const float* __restrict__ as2, const float* __restrict__ ad2) {
    int n = blockIdx.x * 8 + (threadIdx.x >> 5);
    if (n >= NN) return;
    int lane = threadIdx.x & 31;
    const __half2* hrow = (const __half2*)(g_h2h + (size_t)n * 128);
    float s1 = 0.f, s2 = 0.f;
#pragma unroll
    for (int j = 0; j < 2; j++) {
        float2 hv = __half22float2(hrow[j * 32 + lane]);
        int c = (j * 32 + lane) * 2;
        s1 += hv.x * as2[c] + hv.y * as2[c + 1];
        s2 += hv.x * ad2[c] + hv.y * ad2[c + 1];
    }
    for (int o = 16; o; o >>= 1) {
        s1 += __shfl_down_sync(0xffffffffu, s1, o);
        s2 += __shfl_down_sync(0xffffffffu, s2, o);
    }
    if (lane == 0) { g_asrc2[n] = s1; g_adst2[n] = s2; }
}

// ---------------- fused CSR aggregation: conv1 (warp per node, fp16 msgs) ----
__global__ void k_agg1(const float* __restrict__ b1) {
    int node = blockIdx.x * 8 + (threadIdx.x >> 5);
    if (node >= NN) return;
    int lane = threadIdx.x & 31;
    int h = lane & 3;
    int beg = g_rowptr[node], end = g_rowptr[node + 1];
    float adst = g_adst1[node * 4 + h];
    // phase A: segment max per head (8 edge-lanes x 4 heads)
    float mx = -1e30f;
    for (int i = beg + (lane >> 2); i < end; i += 8) {
        int s = g_csrc[i];
        float x = g_asrc1[s * 4 + h] + adst;
        x = x > 0.f ? x : 0.2f * x;
        mx = fmaxf(mx, x);
    }
    mx = fmaxf(mx, __shfl_xor_sync(0xffffffffu, mx, 4));
    mx = fmaxf(mx, __shfl_xor_sync(0xffffffffu, mx, 8));
    mx = fmaxf(mx, __shfl_xor_sync(0xffffffffu, mx, 16));
    // phase B: denom + weighted message accumulation (half2 gather)
    float den = 0.f;
    float2 acc[8];
#pragma unroll
    for (int j = 0; j < 8; j++) acc[j] = make_float2(0.f, 0.f);
    for (int i = beg; i < end; i++) {
        int s = g_csrc[i];
        float x = g_asrc1[s * 4 + h] + adst;
        x = x > 0.f ? x : 0.2f * x;
        float wv = __expf(x - mx);
        den += wv;
        float wh[4];
        wh[0] = __shfl_sync(0xffffffffu, wv, 0);
        wh[1] = __shfl_sync(0xffffffffu, wv, 1);
        wh[2] = __shfl_sync(0xffffffffu, wv, 2);
        wh[3] = __shfl_sync(0xffffffffu, wv, 3);
        const __half2* hs = (const __half2*)(g_h1h + (size_t)s * 512);
#pragma unroll
        for (int j = 0; j < 8; j++) {
            float2 hv = __half22float2(hs[j * 32 + lane]);
            float ww = wh[j >> 1];
            acc[j].x += ww * hv.x;
            acc[j].y += ww * hv.y;
        }
    }
    __half2* od = (__half2*)(g_out1h + (size_t)node * 512);
#pragma unroll
    for (int j = 0; j < 8; j++) {
        float dh = __shfl_sync(0xffffffffu, den, j >> 1);
        float inv = 1.f / (dh + 1e-16f);
        int c = (j * 32 + lane) * 2;
        float2 bb = *(const float2*)(b1 + c);
        float v0 = acc[j].x * inv + bb.x;
        float v1 = acc[j].y * inv + bb.y;
        v0 = v0 > 0.f ? v0 : expm1f(v0);
        v1 = v1 > 0.f ? v1 : expm1f(v1);
        od[j * 32 + lane] = __floats2half2_rn(v0, v1);
    }
}

// ---------------- fused CSR aggregation: conv2 (warp per node, fp16 msgs) ----
__global__ void k_agg2(const float* __restrict__ b2) {
    int node = blockIdx.x * 8 + (threadIdx.x >> 5);
    if (node >= NN) return;
    int lane = threadIdx.x & 31;
    int beg = g_rowptr[node], end = g_rowptr[node + 1];
    float adst = g_adst2[node];
    float mx = -1e30f;
    for (int i = beg + lane; i < end; i += 32) {
        int s = g_csrc[i];
        float x = g_asrc2[s] + adst;
        x = x > 0.f ? x : 0.2f * x;
        mx = fmaxf(mx, x);
    }
#pragma unroll
    for (int o = 16; o; o >>= 1) mx = fmaxf(mx, __shfl_xor_sync(0xffffffffu, mx, o));
    float den = 0.f;
    float2 acc[2];
    acc[0] = make_float2(0.f, 0.f);
    acc[1] = make_float2(0.f, 0.f);
    for (int i = beg; i < end; i++) {
        int s = g_csrc[i];
        float x = g_asrc2[s] + adst;
        x = x > 0.f ? x : 0.2f * x;
        float w = __expf(x - mx);
        den += w;
        const __half2* hs = (const __half2*)(g_h2h + (size_t)s * 128);
#pragma unroll
        for (int j = 0; j < 2; j++) {
            float2 hv = __half22float2(hs[j * 32 + lane]);
            acc[j].x += w * hv.x;
            acc[j].y += w * hv.y;
        }
    }
    float* od = g_out2 + (size_t)node * 128;
    float inv = 1.f / (den + 1e-16f);
#pragma unroll
    for (int j = 0; j < 2; j++) {
        int c = (j * 32 + lane) * 2;
        float2 bb = *(const float2*)(b2 + c);
        float v0 = acc[j].x * inv + bb.x;
        float v1 = acc[j].y * inv + bb.y;
        v0 = v0 > 0.f ? v0 : expm1f(v0);
        v1 = v1 > 0.f ? v1 : expm1f(v1);
        *(float2*)(od + c) = make_float2(v0, v1);
    }
}

// ---------------- global max pool (block per graph, binary search) -----------
__global__ void k_pool(const int* __restrict__ batch) {
    int g = blockIdx.x, c = threadIdx.x;  // 128 threads
    int lo, hi;
    { int a = 0, b = NN; while (a < b) { int m = (a + b) >> 1; if (batch[m] < g) a = m + 1; else b = m; } lo = a; }
    { int a = lo, b = NN; while (a < b) { int m = (a + b) >> 1; if (batch[m] < g + 1) a = m + 1; else b = m; } hi = a; }
    float mx = -3.4e38f;
    for (int n = lo; n < hi; n++) mx = fmaxf(mx, g_out2[(size_t)n * 128 + c]);
    g_pooled[g * 128 + c] = mx;
}

// ---------------- classifier --------------------------------------------------
__global__ void k_cls(const float* __restrict__ Wc1, const float* __restrict__ bc1,
                      const float* __restrict__ Wc2, const float* __restrict__ bc2,
                      float* __restrict__ out) {
    int g = blockIdx.x;
    int t = threadIdx.x;  // 64
    __shared__ float sp[128];
    __shared__ float sh[64];
    sp[t] = g_pooled[g * 128 + t];
    sp[t + 64] = g_pooled[g * 128 + 64 + t];
    __syncthreads();
    float s = bc1[t];
    for (int k = 0; k < 128; k++) s += sp[k] * Wc1[k * 64 + t];
    sh[t] = fmaxf(s, 0.f);
    __syncthreads();
    if (t < NCLS) {
        float o = bc2[t];
        for (int k = 0; k < 64; k++) o += sh[k] * Wc2[k * NCLS + t];
        out[g * NCLS + t] = o;
    }
}

// ---------------- launch ------------------------------------------------------
extern "C" void kernel_launch(void* const* d_in, const int* in_sizes, int n_in,
                              void* d_out, int out_size) {
    const float* xs    = (const float*)d_in[0];
    const int*   xop   = (const int*)d_in[1];
    const int*   xsrc  = (const int*)d_in[2];
    const int*   xsink = (const int*)d_in[3];
    const int*   xstr  = (const int*)d_in[4];
    const int*   xpay  = (const int*)d_in[5];
    const int*   ei    = (const int*)d_in[6];
    const int*   batch = (const int*)d_in[7];
    const float* eop   = (const float*)d_in[8];
    const float* esrc  = (const float*)d_in[9];
    const float* esink = (const float*)d_in[10];
    const float* estr  = (const float*)d_in[11];
    const float* epay  = (const float*)d_in[12];
    const float* ln_g  = (const float*)d_in[13];
    const float* ln_b  = (const float*)d_in[14];
    const float* W1    = (const float*)d_in[15];
    const float* as1   = (const float*)d_in[16];
    const float* ad1   = (const float*)d_in[17];
    const float* b1    = (const float*)d_in[18];
    const float* W2    = (const float*)d_in[19];
    const float* as2   = (const float*)d_in[20];
    const float* ad2   = (const float*)d_in[21];
    const float* b2    = (const float*)d_in[22];
    const float* Wc1   = (const float*)d_in[23];
    const float* bc1   = (const float*)d_in[24];
    const float* Wc2   = (const float*)d_in[25];
    const float* bc2   = (const float*)d_in[26];
    float* out = (float*)d_out;

    float *p_feats;
    __half *p_h1h, *p_out1h, *p_h2h;
    cudaGetSymbolAddress((void**)&p_feats, g_feats);
    cudaGetSymbolAddress((void**)&p_h1h, g_h1h);
    cudaGetSymbolAddress((void**)&p_out1h, g_out1h);
    cudaGetSymbolAddress((void**)&p_h2h, g_h2h);

    int eb = (ET + 255) / 256;
    int nwb = (NN + 7) / 8;  // warp-per-node blocks (256 thr)

    // CSR build
    k_zero_deg<<<(NN + 255) / 256, 256>>>();
    k_deg<<<eb, 256>>>(ei);
    k_scan<<<1, 1024>>>();
    k_fill<<<eb, 256>>>(ei);

    // features (+ fused conv1 logits; needs P1 first)
    k_prep1<<<8, 256>>>(W1, as1, ad1);
    k_feats<<<NN, 256>>>(xs, xop, xsrc, xsink, xstr, xpay,
                         eop, esrc, esink, estr, epay, ln_g, ln_b);

    // conv1
    {
        dim3 grid(512 / 128, (NN + 127) / 128);
        k_mma<float><<<grid, 256>>>(p_feats, W1, p_h1h, NN, 512, 256);
    }
    k_agg1<<<nwb, 256>>>(b1);

    // conv2
    {
        dim3 grid(1, (NN + 127) / 128);
        k_mma<__half><<<grid, 256>>>(p_out1h, W2, p_h2h, NN, 128, 512);
    }
    k_att2<<<nwb, 256>>>(as2, ad2);
    k_agg2<<<nwb, 256>>>(b2);

    // pool + classify
    k_pool<<<GG, 128>>>(batch);
    k_cls<<<GG, 64>>>(Wc1, bc1, Wc2, bc2, out);
}

// round 7
// speedup vs baseline: 3.2613x; 1.0074x over previous
#include <cuda_runtime.h>
#include <cuda_fp16.h>
#include <math.h>
#include <stdint.h>

#define NN 50000
#define EE 500000
#define ET (EE + NN)
#define GG 64
#define SCAL 96
#define DD 32
#define INDIM 256
#define CC 128
#define H1N 4
#define NCLS 5

// ---------------- scratch (device globals; no allocation allowed) ----------
__device__ __half g_featsh[NN * INDIM];      // [N,256] fp16
__device__ __half g_h1h[NN * H1N * CC];      // [N,512] fp16
__device__ __half g_out1h[NN * H1N * CC];    // [N,512] fp16
__device__ __half g_h2h[NN * CC];            // [N,128] fp16
__device__ float  g_out2[NN * CC];           // [N,128] fp32 (feeds pool)
__device__ float  g_asrc1[NN * H1N];
__device__ float  g_adst1[NN * H1N];
__device__ float  g_asrc2[NN];
__device__ float  g_adst2[NN];
__device__ float  g_pooled[GG * CC];
__device__ float  g_P1[INDIM * 8];           // [k][j]  j = h*2 + (0:src,1:dst)
// CSR scratch
__device__ int g_deg[NN];
__device__ int g_rowptr[NN + 1];
__device__ int g_cursor[NN];
__device__ int g_csrc[ET];

// ---------------- CSR build -------------------------------------------------
__global__ void k_zero_deg() {
    int i = blockIdx.x * blockDim.x + threadIdx.x;
    if (i < NN) g_deg[i] = 0;
}

__global__ void k_deg(const int* __restrict__ ei) {
    int e = blockIdx.x * blockDim.x + threadIdx.x;
    if (e >= ET) return;
    int d = (e < EE) ? ei[EE + e] : (e - EE);
    atomicAdd(&g_deg[d], 1);
}

__global__ void k_scan() {
    __shared__ int sh[1024];
    int t = threadIdx.x;
    const int CH = 49;  // 1024*49 >= 50000
    int start = t * CH;
    int s = 0;
    for (int i = start; i < start + CH && i < NN; i++) s += g_deg[i];
    sh[t] = s;
    __syncthreads();
    for (int o = 1; o < 1024; o <<= 1) {
        int v = (t >= o) ? sh[t - o] : 0;
        __syncthreads();
        sh[t] += v;
        __syncthreads();
    }
    int run = sh[t] - s;  // exclusive prefix of this chunk
    for (int i = start; i < start + CH && i < NN; i++) {
        g_rowptr[i] = run;
        g_cursor[i] = run;
        run += g_deg[i];
    }
    if (t == 1023) g_rowptr[NN] = sh[1023];
}

__global__ void k_fill(const int* __restrict__ ei) {
    int e = blockIdx.x * blockDim.x + threadIdx.x;
    if (e >= ET) return;
    int s, d;
    if (e < EE) { s = ei[e]; d = ei[EE + e]; } else { s = d = e - EE; }
    int pos = atomicAdd(&g_cursor[d], 1);
    g_csrc[pos] = s;
}

// ---------------- attention projection prep (runs BEFORE k_feats) -----------
__global__ void k_prep1(const float* __restrict__ W1, const float* __restrict__ as1,
                        const float* __restrict__ ad1) {
    int idx = blockIdx.x * 256 + threadIdx.x;  // 2048
    if (idx >= 2048) return;
    int kk = idx >> 3, j = idx & 7, h = j >> 1;
    const float* av = (j & 1) ? ad1 : as1;
    float s = 0.f;
    for (int c = 0; c < 128; c++) s += W1[kk * 512 + h * 128 + c] * av[h * 128 + c];
    g_P1[kk * 8 + j] = s;
}

// ---------------- feature build + LN + fused conv1 attention logits ---------
__global__ void k_feats(const float* __restrict__ xs,
                        const int* __restrict__ xop, const int* __restrict__ xsrc,
                        const int* __restrict__ xsink, const int* __restrict__ xstr,
                        const int* __restrict__ xpay,
                        const float* __restrict__ eop, const float* __restrict__ esrc,
                        const float* __restrict__ esink, const float* __restrict__ estr,
                        const float* __restrict__ epay,
                        const float* __restrict__ ln_g, const float* __restrict__ ln_b) {
    int n = blockIdx.x;
    int t = threadIdx.x;  // 256 threads
    int w = t >> 5, lane = t & 31;
    float v;
    if (t < SCAL) {
        v = xs[n * SCAL + t];
    } else {
        int grp = (t - SCAL) / DD;
        int d = (t - SCAL) % DD;
        const int* idxp; const float* tab; int L;
        switch (grp) {
            case 0: idxp = xop + n * 16; tab = eop; L = 16; break;
            case 1: idxp = xsrc + n * 8; tab = esrc; L = 8; break;
            case 2: idxp = xsink + n * 8; tab = esink; L = 8; break;
            case 3: idxp = xstr + n * 8; tab = estr; L = 8; break;
            default: idxp = xpay + n * 8; tab = epay; L = 8; break;
        }
        float s = 0.f, cnt = 0.f;
        for (int l = 0; l < L; l++) {
            int id = idxp[l];
            if (id != 0) { s += tab[id * DD + d]; cnt += 1.f; }
        }
        v = s / (cnt + 1e-9f);
    }
    // single-pass LN stats: warp reduce sum & sumsq, one sync
    __shared__ float smA[8], smB[8];
    __shared__ float sm8[8][8];
    float s1 = v, s2 = v * v;
#pragma unroll
    for (int o = 16; o; o >>= 1) {
        s1 += __shfl_xor_sync(0xffffffffu, s1, o);
        s2 += __shfl_xor_sync(0xffffffffu, s2, o);
    }
    if (lane == 0) { smA[w] = s1; smB[w] = s2; }
    __syncthreads();
    float S = 0.f, S2 = 0.f;
#pragma unroll
    for (int i = 0; i < 8; i++) { S += smA[i]; S2 += smB[i]; }
    float mu = S * (1.f / 256.f);
    float var = S2 * (1.f / 256.f) - mu * mu;
    float o = (v - mu) * rsqrtf(var + 1e-5f) * ln_g[t] + ln_b[t];
    g_featsh[n * INDIM + t] = __float2half_rn(o);
    // fused conv1 attention logits: acc_j = sum_k o_k * P1[k][j]
    float pj[8];
#pragma unroll
    for (int j = 0; j < 8; j++) pj[j] = o * g_P1[t * 8 + j];
#pragma unroll
    for (int j = 0; j < 8; j++)
#pragma unroll
        for (int off = 16; off; off >>= 1) pj[j] += __shfl_xor_sync(0xffffffffu, pj[j], off);
    if (lane == 0) {
#pragma unroll
        for (int j = 0; j < 8; j++) sm8[w][j] = pj[j];
    }
    __syncthreads();
    if (t < 8) {
        float s = 0.f;
#pragma unroll
        for (int i = 0; i < 8; i++) s += sm8[i][t];
        int h = t >> 1;
        if (t & 1) g_adst1[n * 4 + h] = s;
        else       g_asrc1[n * 4 + h] = s;
    }
}

// ---------------- fp16 tensor-core GEMM: C[M,N]=A[M,K]@B[K,N] ---------------
// A fp16 row-major, B fp32 row-major (converted), C fp16. fp32 accumulation.
// BM=128 BN=128 BK=32, 256 threads = 8 warps (4x2), warp tile 32x64.
// Double-buffered smem, one sync per k-step.
#define MMA_F16(d0,d1,d2,d3,a0,a1,a2,a3,b0,b1) \
    asm volatile("mma.sync.aligned.m16n8k16.row.col.f32.f16.f16.f32 " \
                 "{%0,%1,%2,%3},{%4,%5,%6,%7},{%8,%9},{%0,%1,%2,%3};" \
                 : "+f"(d0), "+f"(d1), "+f"(d2), "+f"(d3) \
                 : "r"(a0), "r"(a1), "r"(a2), "r"(a3), "r"(b0), "r"(b1))

__device__ __forceinline__ uint32_t pack_h2(float x, float y) {
    __half2 h = __floats2half2_rn(x, y);
    return *(uint32_t*)&h;
}

__global__ void __launch_bounds__(256) k_hgemm(const __half* __restrict__ A,
                                               const float* __restrict__ B,
                                               __half* __restrict__ C, int M, int N, int K) {
    // [buf][row][half2-k], pitch 20 words -> conflict-free fragment reads
    __shared__ uint32_t As2[2][128][20];
    __shared__ uint32_t Bs2[2][128][20];
    int tid = threadIdx.x;
    int wid = tid >> 5, lane = tid & 31;
    int wm = (wid & 3) * 32;
    int wn = (wid >> 2) * 64;
    int gid = lane >> 2, tig = lane & 3;
    int row0 = blockIdx.y * 128, col0 = blockIdx.x * 128;
    float acc[2][8][4];
#pragma unroll
    for (int i = 0; i < 2; i++)
#pragma unroll
        for (int j = 0; j < 8; j++)
#pragma unroll
            for (int q = 0; q < 4; q++) acc[i][j][q] = 0.f;

    int T = K >> 5;  // k-steps of 32
    // preload tile 0
    {
        int k0 = 0;
#pragma unroll
        for (int r = 0; r < 8; r++) {
            int u = tid + 256 * r;
            int m = u >> 4, q = u & 15;
            int gm = row0 + m;
            As2[0][m][q] = (gm < M) ? ((const uint32_t*)(A + (size_t)gm * K + k0))[q] : 0u;
        }
#pragma unroll
        for (int r = 0; r < 8; r++) {
            int u = tid + 256 * r;
            int n = u & 127, q = u >> 7;
            float b0v = B[(size_t)(k0 + 2 * q) * N + col0 + n];
            float b1v = B[(size_t)(k0 + 2 * q + 1) * N + col0 + n];
            Bs2[0][n][q] = pack_h2(b0v, b1v);
        }
    }
    __syncthreads();

    for (int t = 0; t < T; t++) {
        int cur = t & 1;
        uint32_t ra[8], rb[8];
        if (t + 1 < T) {
            int k0 = (t + 1) << 5;
#pragma unroll
            for (int r = 0; r < 8; r++) {
                int u = tid + 256 * r;
                int m = u >> 4, q = u & 15;
                int gm = row0 + m;
                ra[r] = (gm < M) ? ((const uint32_t*)(A + (size_t)gm * K + k0))[q] : 0u;
            }
#pragma unroll
            for (int r = 0; r < 8; r++) {
                int u = tid + 256 * r;
                int n = u & 127, q = u >> 7;
                float b0v = B[(size_t)(k0 + 2 * q) * N + col0 + n];
                float b1v = B[(size_t)(k0 + 2 * q + 1) * N + col0 + n];
                rb[r] = pack_h2(b0v, b1v);
            }
        }
        // compute on cur
#pragma unroll
        for (int ks = 0; ks < 2; ks++) {
            int kb = ks * 8;
            uint32_t a[2][4];
#pragma unroll
            for (int mi = 0; mi < 2; mi++) {
                int r = wm + mi * 16 + gid;
                a[mi][0] = As2[cur][r][kb + tig];
                a[mi][1] = As2[cur][r + 8][kb + tig];
                a[mi][2] = As2[cur][r][kb + tig + 4];
                a[mi][3] = As2[cur][r + 8][kb + tig + 4];
            }
#pragma unroll
            for (int ni = 0; ni < 8; ni++) {
                uint32_t b0 = Bs2[cur][wn + ni * 8 + gid][kb + tig];
                uint32_t b1 = Bs2[cur][wn + ni * 8 + gid][kb + tig + 4];
#pragma unroll
                for (int mi = 0; mi < 2; mi++) {
                    MMA_F16(acc[mi][ni][0], acc[mi][ni][1], acc[mi][ni][2], acc[mi][ni][3],
                            a[mi][0], a[mi][1], a[mi][2], a[mi][3], b0, b1);
                }
            }
        }
        if (t + 1 < T) {
            int nxt = 1 - cur;
#pragma unroll
            for (int r = 0; r < 8; r++) {
                int u = tid + 256 * r;
                int m = u >> 4, q = u & 15;
                As2[nxt][m][q] = ra[r];
            }
#pragma unroll
            for (int r = 0; r < 8; r++) {
                int u = tid + 256 * r;
                int n = u & 127, q = u >> 7;
                Bs2[nxt][n][q] = rb[r];
            }
        }
        __syncthreads();
    }
#pragma unroll
    for (int mi = 0; mi < 2; mi++) {
#pragma unroll
        for (int ni = 0; ni < 8; ni++) {
            int r = row0 + wm + mi * 16 + gid;
            int c = col0 + wn + ni * 8 + tig * 2;
            if (r < M)
                *(__half2*)(C + (size_t)r * N + c) = __floats2half2_rn(acc[mi][ni][0], acc[mi][ni][1]);
            if (r + 8 < M)
                *(__half2*)(C + (size_t)(r + 8) * N + c) = __floats2half2_rn(acc[mi][ni][2], acc[mi][ni][3]);
        }
    }
}

// ---------------- conv2 attention logits (reads fp16 h2) --------------------
__global__ void k_att2(const float* __restrict__ as2, const float* __restrict__ ad2) {
    int n = blockIdx.x * 8 + (threadIdx.x >> 5);
    if (n >= NN) return;
    int lane = threadIdx.x & 31;
    const __half2* hrow = (const __half2*)(g_h2h + (size_t)n * 128);
    float s1 = 0.f, s2 = 0.f;
#pragma unroll
    for (int j = 0; j < 2; j++) {
        float2 hv = __half22float2(hrow[j * 32 + lane]);
        int c = (j * 32 + lane) * 2;
        s1 += hv.x * as2[c] + hv.y * as2[c + 1];
        s2 += hv.x * ad2[c] + hv.y * ad2[c + 1];
    }
    for (int o = 16; o; o >>= 1) {
        s1 += __shfl_down_sync(0xffffffffu, s1, o);
        s2 += __shfl_down_sync(0xffffffffu, s2, o);
    }
    if (lane == 0) { g_asrc2[n] = s1; g_adst2[n] = s2; }
}

// ---------------- fused CSR aggregation: conv1 (warp per node, fp16 msgs) ----
__global__ void k_agg1(const float* __restrict__ b1) {
    int node = blockIdx.x * 8 + (threadIdx.x >> 5);
    if (node >= NN) return;
    int lane = threadIdx.x & 31;
    int h = lane & 3;
    int beg = g_rowptr[node], end = g_rowptr[node + 1];
    float adst = g_adst1[node * 4 + h];
    // phase A: segment max per head (8 edge-lanes x 4 heads)
    float mx = -1e30f;
    for (int i = beg + (lane >> 2); i < end; i += 8) {
        int s = g_csrc[i];
        float x = g_asrc1[s * 4 + h] + adst;
        x = x > 0.f ? x : 0.2f * x;
        mx = fmaxf(mx, x);
    }
    mx = fmaxf(mx, __shfl_xor_sync(0xffffffffu, mx, 4));
    mx = fmaxf(mx, __shfl_xor_sync(0xffffffffu, mx, 8));
    mx = fmaxf(mx, __shfl_xor_sync(0xffffffffu, mx, 16));
    // phase B: denom + weighted message accumulation (half2 gather)
    float den = 0.f;
    float2 acc[8];
#pragma unroll
    for (int j = 0; j < 8; j++) acc[j] = make_float2(0.f, 0.f);
    for (int i = beg; i < end; i++) {
        int s = g_csrc[i];
        float x = g_asrc1[s * 4 + h] + adst;
        x = x > 0.f ? x : 0.2f * x;
        float wv = __expf(x - mx);
        den += wv;
        float wh[4];
        wh[0] = __shfl_sync(0xffffffffu, wv, 0);
        wh[1] = __shfl_sync(0xffffffffu, wv, 1);
        wh[2] = __shfl_sync(0xffffffffu, wv, 2);
        wh[3] = __shfl_sync(0xffffffffu, wv, 3);
        const __half2* hs = (const __half2*)(g_h1h + (size_t)s * 512);
#pragma unroll
        for (int j = 0; j < 8; j++) {
            float2 hv = __half22float2(hs[j * 32 + lane]);
            float ww = wh[j >> 1];
            acc[j].x += ww * hv.x;
            acc[j].y += ww * hv.y;
        }
    }
    __half2* od = (__half2*)(g_out1h + (size_t)node * 512);
#pragma unroll
    for (int j = 0; j < 8; j++) {
        float dh = __shfl_sync(0xffffffffu, den, j >> 1);
        float inv = 1.f / (dh + 1e-16f);
        int c = (j * 32 + lane) * 2;
        float2 bb = *(const float2*)(b1 + c);
        float v0 = acc[j].x * inv + bb.x;
        float v1 = acc[j].y * inv + bb.y;
        v0 = v0 > 0.f ? v0 : expm1f(v0);
        v1 = v1 > 0.f ? v1 : expm1f(v1);
        od[j * 32 + lane] = __floats2half2_rn(v0, v1);
    }
}

// ---------------- fused CSR aggregation: conv2 (warp per node, fp16 msgs) ----
__global__ void k_agg2(const float* __restrict__ b2) {
    int node = blockIdx.x * 8 + (threadIdx.x >> 5);
    if (node >= NN) return;
    int lane = threadIdx.x & 31;
    int beg = g_rowptr[node], end = g_rowptr[node + 1];
    float adst = g_adst2[node];
    float mx = -1e30f;
    for (int i = beg + lane; i < end; i += 32) {
        int s = g_csrc[i];
        float x = g_asrc2[s] + adst;
        x = x > 0.f ? x : 0.2f * x;
        mx = fmaxf(mx, x);
    }
#pragma unroll
    for (int o = 16; o; o >>= 1) mx = fmaxf(mx, __shfl_xor_sync(0xffffffffu, mx, o));
    float den = 0.f;
    float2 acc[2];
    acc[0] = make_float2(0.f, 0.f);
    acc[1] = make_float2(0.f, 0.f);
    for (int i = beg; i < end; i++) {
        int s = g_csrc[i];
        float x = g_asrc2[s] + adst;
        x = x > 0.f ? x : 0.2f * x;
        float w = __expf(x - mx);
        den += w;
        const __half2* hs = (const __half2*)(g_h2h + (size_t)s * 128);
#pragma unroll
        for (int j = 0; j < 2; j++) {
            float2 hv = __half22float2(hs[j * 32 + lane]);
            acc[j].x += w * hv.x;
            acc[j].y += w * hv.y;
        }
    }
    float* od = g_out2 + (size_t)node * 128;
    float inv = 1.f / (den + 1e-16f);
#pragma unroll
    for (int j = 0; j < 2; j++) {
        int c = (j * 32 + lane) * 2;
        float2 bb = *(const float2*)(b2 + c);
        float v0 = acc[j].x * inv + bb.x;
        float v1 = acc[j].y * inv + bb.y;
        v0 = v0 > 0.f ? v0 : expm1f(v0);
        v1 = v1 > 0.f ? v1 : expm1f(v1);
        *(float2*)(od + c) = make_float2(v0, v1);
    }
}

// ---------------- global max pool (block per graph, binary search) -----------
__global__ void k_pool(const int* __restrict__ batch) {
    int g = blockIdx.x, c = threadIdx.x;  // 128 threads
    int lo, hi;
    { int a = 0, b = NN; while (a < b) { int m = (a + b) >> 1; if (batch[m] < g) a = m + 1; else b = m; } lo = a; }
    { int a = lo, b = NN; while (a < b) { int m = (a + b) >> 1; if (batch[m] < g + 1) a = m + 1; else b = m; } hi = a; }
    float mx = -3.4e38f;
    for (int n = lo; n < hi; n++) mx = fmaxf(mx, g_out2[(size_t)n * 128 + c]);
    g_pooled[g * 128 + c] = mx;
}

// ---------------- classifier --------------------------------------------------
__global__ void k_cls(const float* __restrict__ Wc1, const float* __restrict__ bc1,
                      const float* __restrict__ Wc2, const float* __restrict__ bc2,
                      float* __restrict__ out) {
    int g = blockIdx.x;
    int t = threadIdx.x;  // 64
    __shared__ float sp[128];
    __shared__ float sh[64];
    sp[t] = g_pooled[g * 128 + t];
    sp[t + 64] = g_pooled[g * 128 + 64 + t];
    __syncthreads();
    float s = bc1[t];
    for (int k = 0; k < 128; k++) s += sp[k] * Wc1[k * 64 + t];
    sh[t] = fmaxf(s, 0.f);
    __syncthreads();
    if (t < NCLS) {
        float o = bc2[t];
        for (int k = 0; k < 64; k++) o += sh[k] * Wc2[k * NCLS + t];
        out[g * NCLS + t] = o;
    }
}

// ---------------- launch ------------------------------------------------------
extern "C" void kernel_launch(void* const* d_in, const int* in_sizes, int n_in,
                              void* d_out, int out_size) {
    const float* xs    = (const float*)d_in[0];
    const int*   xop   = (const int*)d_in[1];
    const int*   xsrc  = (const int*)d_in[2];
    const int*   xsink = (const int*)d_in[3];
    const int*   xstr  = (const int*)d_in[4];
    const int*   xpay  = (const int*)d_in[5];
    const int*   ei    = (const int*)d_in[6];
    const int*   batch = (const int*)d_in[7];
    const float* eop   = (const float*)d_in[8];
    const float* esrc  = (const float*)d_in[9];
    const float* esink = (const float*)d_in[10];
    const float* estr  = (const float*)d_in[11];
    const float* epay  = (const float*)d_in[12];
    const float* ln_g  = (const float*)d_in[13];
    const float* ln_b  = (const float*)d_in[14];
    const float* W1    = (const float*)d_in[15];
    const float* as1   = (const float*)d_in[16];
    const float* ad1   = (const float*)d_in[17];
    const float* b1    = (const float*)d_in[18];
    const float* W2    = (const float*)d_in[19];
    const float* as2   = (const float*)d_in[20];
    const float* ad2   = (const float*)d_in[21];
    const float* b2    = (const float*)d_in[22];
    const float* Wc1   = (const float*)d_in[23];
    const float* bc1   = (const float*)d_in[24];
    const float* Wc2   = (const float*)d_in[25];
    const float* bc2   = (const float*)d_in[26];
    float* out = (float*)d_out;

    __half *p_featsh, *p_h1h, *p_out1h, *p_h2h;
    cudaGetSymbolAddress((void**)&p_featsh, g_featsh);
    cudaGetSymbolAddress((void**)&p_h1h, g_h1h);
    cudaGetSymbolAddress((void**)&p_out1h, g_out1h);
    cudaGetSymbolAddress((void**)&p_h2h, g_h2h);

    int eb = (ET + 255) / 256;
    int nwb = (NN + 7) / 8;  // warp-per-node blocks (256 thr)

    // CSR build
    k_zero_deg<<<(NN + 255) / 256, 256>>>();
    k_deg<<<eb, 256>>>(ei);
    k_scan<<<1, 1024>>>();
    k_fill<<<eb, 256>>>(ei);

    // features (+ fused conv1 logits; needs P1 first)
    k_prep1<<<8, 256>>>(W1, as1, ad1);
    k_feats<<<NN, 256>>>(xs, xop, xsrc, xsink, xstr, xpay,
                         eop, esrc, esink, estr, epay, ln_g, ln_b);

    // conv1
    {
        dim3 grid(512 / 128, (NN + 127) / 128);
        k_hgemm<<<grid, 256>>>(p_featsh, W1, p_h1h, NN, 512, 256);
    }
    k_agg1<<<nwb, 256>>>(b1);

    // conv2
    {
        dim3 grid(1, (NN + 127) / 128);
        k_hgemm<<<grid, 256>>>(p_out1h, W2, p_h2h, NN, 128, 512);
    }
    k_att2<<<nwb, 256>>>(as2, ad2);
    k_agg2<<<nwb, 256>>>(b2);

    // pool + classify
    k_pool<<<GG, 128>>>(batch);
    k_cls<<<GG, 64>>>(Wc1, bc1, Wc2, bc2, out);
}

// round 8
// speedup vs baseline: 3.6177x; 1.1093x over previous
#include <cuda_runtime.h>
#include <cuda_fp16.h>
#include <math.h>
#include <stdint.h>

#define NN 50000
#define EE 500000
#define ET (EE + NN)
#define GG 64
#define SCAL 96
#define DD 32
#define INDIM 256
#define CC 128
#define H1N 4
#define NCLS 5

// ---------------- scratch (device globals; no allocation allowed) ----------
__device__ __half g_featsh[NN * INDIM];      // [N,256] fp16
__device__ __half g_h1h[NN * H1N * CC];      // [N,512] fp16
__device__ __half g_out1h[NN * H1N * CC];    // [N,512] fp16
__device__ __half g_h2h[NN * CC];            // [N,128] fp16
__device__ float  g_out2[NN * CC];           // [N,128] fp32 (feeds pool)
__device__ float  g_asrc1[NN * H1N];
__device__ float  g_adst1[NN * H1N];
__device__ float  g_asrc2[NN];
__device__ float  g_adst2[NN];
__device__ float  g_pooled[GG * CC];
__device__ float  g_P1[INDIM * 8];           // [k][j]  j = h*2 + (0:src,1:dst)
// CSR scratch
__device__ int g_deg[NN];
__device__ int g_rowptr[NN + 1];
__device__ int g_cursor[NN];
__device__ int g_csrc[ET];

__device__ __forceinline__ void atomicMaxF(float* addr, float val) {
    int* ia = (int*)addr;
    int old = *ia;
    while (__int_as_float(old) < val) {
        int assumed = old;
        old = atomicCAS(ia, assumed, __float_as_int(val));
        if (old == assumed) break;
    }
}

// ---------------- fused init: zero deg, init pooled, prep1 ------------------
__global__ void k_init(const float* __restrict__ W1, const float* __restrict__ as1,
                       const float* __restrict__ ad1) {
    int idx = blockIdx.x * 256 + threadIdx.x;
    if (idx < NN) g_deg[idx] = 0;
    if (idx < GG * CC) g_pooled[idx] = -3.0e38f;
    if (idx < 2048) {
        int kk = idx >> 3, j = idx & 7, h = j >> 1;
        const float* av = (j & 1) ? ad1 : as1;
        float s = 0.f;
        for (int c = 0; c < 128; c++) s += W1[kk * 512 + h * 128 + c] * av[h * 128 + c];
        g_P1[kk * 8 + j] = s;
    }
}

// ---------------- CSR build -------------------------------------------------
__global__ void k_deg(const int* __restrict__ ei) {
    int e = blockIdx.x * blockDim.x + threadIdx.x;
    if (e >= ET) return;
    int d = (e < EE) ? ei[EE + e] : (e - EE);
    atomicAdd(&g_deg[d], 1);
}

// single block, 1024 threads = 32 warps, coalesced two-phase scan
__global__ void k_scan() {
    __shared__ int wsum[32], wbase[32];
    int t = threadIdx.x, w = t >> 5, lane = t & 31;
    const int CHUNK = 1568;  // 32*49; 32*1568 = 50176 >= 50000
    int start = w * CHUNK;
    int lim = start + CHUNK; if (lim > NN) lim = NN;
    // phase 1: warp chunk sums (coalesced)
    int s = 0;
    for (int i = start + lane; i < lim; i += 32) s += g_deg[i];
#pragma unroll
    for (int o = 16; o; o >>= 1) s += __shfl_xor_sync(0xffffffffu, s, o);
    if (lane == 0) wsum[w] = s;
    __syncthreads();
    // phase 2: scan warp sums
    if (w == 0) {
        int v = wsum[lane];
        int incl = v;
#pragma unroll
        for (int o = 1; o < 32; o <<= 1) {
            int u = __shfl_up_sync(0xffffffffu, incl, o);
            if (lane >= o) incl += u;
        }
        wbase[lane] = incl - v;
        if (lane == 31) g_rowptr[NN] = incl;
    }
    __syncthreads();
    // phase 3: per-warp running scan, coalesced
    int running = wbase[w];
    for (int i0 = start; i0 < lim; i0 += 32) {
        int idx = i0 + lane;
        int v = (idx < lim) ? g_deg[idx] : 0;
        int incl = v;
#pragma unroll
        for (int o = 1; o < 32; o <<= 1) {
            int u = __shfl_up_sync(0xffffffffu, incl, o);
            if (lane >= o) incl += u;
        }
        int excl = incl - v;
        if (idx < lim) { g_rowptr[idx] = running + excl; g_cursor[idx] = running + excl; }
        running += __shfl_sync(0xffffffffu, incl, 31);
    }
}

__global__ void k_fill(const int* __restrict__ ei) {
    int e = blockIdx.x * blockDim.x + threadIdx.x;
    if (e >= ET) return;
    int s, d;
    if (e < EE) { s = ei[e]; d = ei[EE + e]; } else { s = d = e - EE; }
    int pos = atomicAdd(&g_cursor[d], 1);
    g_csrc[pos] = s;
}

// ---------------- feature build + LN + fused conv1 attention logits ---------
__global__ void k_feats(const float* __restrict__ xs,
                        const int* __restrict__ xop, const int* __restrict__ xsrc,
                        const int* __restrict__ xsink, const int* __restrict__ xstr,
                        const int* __restrict__ xpay,
                        const float* __restrict__ eop, const float* __restrict__ esrc,
                        const float* __restrict__ esink, const float* __restrict__ estr,
                        const float* __restrict__ epay,
                        const float* __restrict__ ln_g, const float* __restrict__ ln_b) {
    int n = blockIdx.x;
    int t = threadIdx.x;  // 256 threads
    int w = t >> 5, lane = t & 31;
    float v;
    if (t < SCAL) {
        v = xs[n * SCAL + t];
    } else {
        int grp = (t - SCAL) / DD;
        int d = (t - SCAL) % DD;
        const int* idxp; const float* tab; int L;
        switch (grp) {
            case 0: idxp = xop + n * 16; tab = eop; L = 16; break;
            case 1: idxp = xsrc + n * 8; tab = esrc; L = 8; break;
            case 2: idxp = xsink + n * 8; tab = esink; L = 8; break;
            case 3: idxp = xstr + n * 8; tab = estr; L = 8; break;
            default: idxp = xpay + n * 8; tab = epay; L = 8; break;
        }
        float s = 0.f, cnt = 0.f;
        for (int l = 0; l < L; l++) {
            int id = idxp[l];
            if (id != 0) { s += tab[id * DD + d]; cnt += 1.f; }
        }
        v = s / (cnt + 1e-9f);
    }
    __shared__ float smA[8], smB[8];
    __shared__ float sm8[8][8];
    float s1 = v, s2 = v * v;
#pragma unroll
    for (int o = 16; o; o >>= 1) {
        s1 += __shfl_xor_sync(0xffffffffu, s1, o);
        s2 += __shfl_xor_sync(0xffffffffu, s2, o);
    }
    if (lane == 0) { smA[w] = s1; smB[w] = s2; }
    __syncthreads();
    float S = 0.f, S2 = 0.f;
#pragma unroll
    for (int i = 0; i < 8; i++) { S += smA[i]; S2 += smB[i]; }
    float mu = S * (1.f / 256.f);
    float var = S2 * (1.f / 256.f) - mu * mu;
    float o = (v - mu) * rsqrtf(var + 1e-5f) * ln_g[t] + ln_b[t];
    g_featsh[n * INDIM + t] = __float2half_rn(o);
    float pj[8];
#pragma unroll
    for (int j = 0; j < 8; j++) pj[j] = o * g_P1[t * 8 + j];
#pragma unroll
    for (int j = 0; j < 8; j++)
#pragma unroll
        for (int off = 16; off; off >>= 1) pj[j] += __shfl_xor_sync(0xffffffffu, pj[j], off);
    if (lane == 0) {
#pragma unroll
        for (int j = 0; j < 8; j++) sm8[w][j] = pj[j];
    }
    __syncthreads();
    if (t < 8) {
        float s = 0.f;
#pragma unroll
        for (int i = 0; i < 8; i++) s += sm8[i][t];
        int h = t >> 1;
        if (t & 1) g_adst1[n * 4 + h] = s;
        else       g_asrc1[n * 4 + h] = s;
    }
}

// ---------------- fp16 tensor-core GEMM: C[M,N]=A[M,K]@B[K,N] ---------------
#define MMA_F16(d0,d1,d2,d3,a0,a1,a2,a3,b0,b1) \
    asm volatile("mma.sync.aligned.m16n8k16.row.col.f32.f16.f16.f32 " \
                 "{%0,%1,%2,%3},{%4,%5,%6,%7},{%8,%9},{%0,%1,%2,%3};" \
                 : "+f"(d0), "+f"(d1), "+f"(d2), "+f"(d3) \
                 : "r"(a0), "r"(a1), "r"(a2), "r"(a3), "r"(b0), "r"(b1))

__device__ __forceinline__ uint32_t pack_h2(float x, float y) {
    __half2 h = __floats2half2_rn(x, y);
    return *(uint32_t*)&h;
}

__global__ void __launch_bounds__(256) k_hgemm(const __half* __restrict__ A,
                                               const float* __restrict__ B,
                                               __half* __restrict__ C, int M, int N, int K) {
    __shared__ uint32_t As2[2][128][20];
    __shared__ uint32_t Bs2[2][128][20];
    int tid = threadIdx.x;
    int wid = tid >> 5, lane = tid & 31;
    int wm = (wid & 3) * 32;
    int wn = (wid >> 2) * 64;
    int gid = lane >> 2, tig = lane & 3;
    int row0 = blockIdx.y * 128, col0 = blockIdx.x * 128;
    float acc[2][8][4];
#pragma unroll
    for (int i = 0; i < 2; i++)
#pragma unroll
        for (int j = 0; j < 8; j++)
#pragma unroll
            for (int q = 0; q < 4; q++) acc[i][j][q] = 0.f;

    int T = K >> 5;
    {
#pragma unroll
        for (int r = 0; r < 8; r++) {
            int u = tid + 256 * r;
            int m = u >> 4, q = u & 15;
            int gm = row0 + m;
            As2[0][m][q] = (gm < M) ? ((const uint32_t*)(A + (size_t)gm * K))[q] : 0u;
        }
#pragma unroll
        for (int r = 0; r < 8; r++) {
            int u = tid + 256 * r;
            int n = u & 127, q = u >> 7;
            float b0v = B[(size_t)(2 * q) * N + col0 + n];
            float b1v = B[(size_t)(2 * q + 1) * N + col0 + n];
            Bs2[0][n][q] = pack_h2(b0v, b1v);
        }
    }
    __syncthreads();

    for (int t = 0; t < T; t++) {
        int cur = t & 1;
        uint32_t ra[8], rb[8];
        if (t + 1 < T) {
            int k0 = (t + 1) << 5;
#pragma unroll
            for (int r = 0; r < 8; r++) {
                int u = tid + 256 * r;
                int m = u >> 4, q = u & 15;
                int gm = row0 + m;
                ra[r] = (gm < M) ? ((const uint32_t*)(A + (size_t)gm * K + k0))[q] : 0u;
            }
#pragma unroll
            for (int r = 0; r < 8; r++) {
                int u = tid + 256 * r;
                int n = u & 127, q = u >> 7;
                float b0v = B[(size_t)(k0 + 2 * q) * N + col0 + n];
                float b1v = B[(size_t)(k0 + 2 * q + 1) * N + col0 + n];
                rb[r] = pack_h2(b0v, b1v);
            }
        }
#pragma unroll
        for (int ks = 0; ks < 2; ks++) {
            int kb = ks * 8;
            uint32_t a[2][4];
#pragma unroll
            for (int mi = 0; mi < 2; mi++) {
                int r = wm + mi * 16 + gid;
                a[mi][0] = As2[cur][r][kb + tig];
                a[mi][1] = As2[cur][r + 8][kb + tig];
                a[mi][2] = As2[cur][r][kb + tig + 4];
                a[mi][3] = As2[cur][r + 8][kb + tig + 4];
            }
#pragma unroll
            for (int ni = 0; ni < 8; ni++) {
                uint32_t b0 = Bs2[cur][wn + ni * 8 + gid][kb + tig];
                uint32_t b1 = Bs2[cur][wn + ni * 8 + gid][kb + tig + 4];
#pragma unroll
                for (int mi = 0; mi < 2; mi++) {
                    MMA_F16(acc[mi][ni][0], acc[mi][ni][1], acc[mi][ni][2], acc[mi][ni][3],
                            a[mi][0], a[mi][1], a[mi][2], a[mi][3], b0, b1);
                }
            }
        }
        if (t + 1 < T) {
            int nxt = 1 - cur;
#pragma unroll
            for (int r = 0; r < 8; r++) {
                int u = tid + 256 * r;
                int m = u >> 4, q = u & 15;
                As2[nxt][m][q] = ra[r];
            }
#pragma unroll
            for (int r = 0; r < 8; r++) {
                int u = tid + 256 * r;
                int n = u & 127, q = u >> 7;
                Bs2[nxt][n][q] = rb[r];
            }
        }
        __syncthreads();
    }
#pragma unroll
    for (int mi = 0; mi < 2; mi++) {
#pragma unroll
        for (int ni = 0; ni < 8; ni++) {
            int r = row0 + wm + mi * 16 + gid;
            int c = col0 + wn + ni * 8 + tig * 2;
            if (r < M)
                *(__half2*)(C + (size_t)r * N + c) = __floats2half2_rn(acc[mi][ni][0], acc[mi][ni][1]);
            if (r + 8 < M)
                *(__half2*)(C + (size_t)(r + 8) * N + c) = __floats2half2_rn(acc[mi][ni][2], acc[mi][ni][3]);
        }
    }
}

// ---------------- conv2 attention logits (reads fp16 h2) --------------------
__global__ void k_att2(const float* __restrict__ as2, const float* __restrict__ ad2) {
    int n = blockIdx.x * 8 + (threadIdx.x >> 5);
    if (n >= NN) return;
    int lane = threadIdx.x & 31;
    const __half2* hrow = (const __half2*)(g_h2h + (size_t)n * 128);
    float s1 = 0.f, s2 = 0.f;
#pragma unroll
    for (int j = 0; j < 2; j++) {
        float2 hv = __half22float2(hrow[j * 32 + lane]);
        int c = (j * 32 + lane) * 2;
        s1 += hv.x * as2[c] + hv.y * as2[c + 1];
        s2 += hv.x * ad2[c] + hv.y * ad2[c + 1];
    }
    for (int o = 16; o; o >>= 1) {
        s1 += __shfl_down_sync(0xffffffffu, s1, o);
        s2 += __shfl_down_sync(0xffffffffu, s2, o);
    }
    if (lane == 0) { g_asrc2[n] = s1; g_adst2[n] = s2; }
}

// ---------------- fused CSR aggregation: conv1 (warp/node, no-max, unroll2) --
__global__ void k_agg1(const float* __restrict__ b1) {
    int node = blockIdx.x * 8 + (threadIdx.x >> 5);
    if (node >= NN) return;
    int lane = threadIdx.x & 31;
    int h = lane & 3;
    int beg = g_rowptr[node], end = g_rowptr[node + 1];
    float adst = g_adst1[node * 4 + h];
    float den = 0.f;
    float2 acc[8];
#pragma unroll
    for (int j = 0; j < 8; j++) acc[j] = make_float2(0.f, 0.f);
    int i = beg;
    for (; i + 2 <= end; i += 2) {
        int s0 = g_csrc[i], s1 = g_csrc[i + 1];
        float x0 = g_asrc1[s0 * 4 + h] + adst;
        x0 = x0 > 0.f ? x0 : 0.2f * x0;
        float w0 = __expf(x0);
        float x1 = g_asrc1[s1 * 4 + h] + adst;
        x1 = x1 > 0.f ? x1 : 0.2f * x1;
        float w1 = __expf(x1);
        den += w0 + w1;
        float wa[4], wb[4];
#pragma unroll
        for (int k = 0; k < 4; k++) {
            wa[k] = __shfl_sync(0xffffffffu, w0, k);
            wb[k] = __shfl_sync(0xffffffffu, w1, k);
        }
        const __half2* h0 = (const __half2*)(g_h1h + (size_t)s0 * 512);
        const __half2* h1p = (const __half2*)(g_h1h + (size_t)s1 * 512);
        __half2 r0[8], r1[8];
#pragma unroll
        for (int j = 0; j < 8; j++) r0[j] = h0[j * 32 + lane];
#pragma unroll
        for (int j = 0; j < 8; j++) r1[j] = h1p[j * 32 + lane];
#pragma unroll
        for (int j = 0; j < 8; j++) {
            float2 f0 = __half22float2(r0[j]);
            float2 f1 = __half22float2(r1[j]);
            float wwa = wa[j >> 1], wwb = wb[j >> 1];
            acc[j].x += wwa * f0.x + wwb * f1.x;
            acc[j].y += wwa * f0.y + wwb * f1.y;
        }
    }
    if (i < end) {
        int s0 = g_csrc[i];
        float x0 = g_asrc1[s0 * 4 + h] + adst;
        x0 = x0 > 0.f ? x0 : 0.2f * x0;
        float w0 = __expf(x0);
        den += w0;
        float wa[4];
#pragma unroll
        for (int k = 0; k < 4; k++) wa[k] = __shfl_sync(0xffffffffu, w0, k);
        const __half2* h0 = (const __half2*)(g_h1h + (size_t)s0 * 512);
#pragma unroll
        for (int j = 0; j < 8; j++) {
            float2 f0 = __half22float2(h0[j * 32 + lane]);
            float ww = wa[j >> 1];
            acc[j].x += ww * f0.x;
            acc[j].y += ww * f0.y;
        }
    }
    __half2* od = (__half2*)(g_out1h + (size_t)node * 512);
#pragma unroll
    for (int j = 0; j < 8; j++) {
        float dh = __shfl_sync(0xffffffffu, den, j >> 1);
        float inv = 1.f / (dh + 1e-16f);
        int c = (j * 32 + lane) * 2;
        float2 bb = *(const float2*)(b1 + c);
        float v0 = acc[j].x * inv + bb.x;
        float v1 = acc[j].y * inv + bb.y;
        v0 = v0 > 0.f ? v0 : expm1f(v0);
        v1 = v1 > 0.f ? v1 : expm1f(v1);
        od[j * 32 + lane] = __floats2half2_rn(v0, v1);
    }
}

// ---------------- fused CSR aggregation: conv2 (warp/node, no-max, unroll2) --
__global__ void k_agg2(const float* __restrict__ b2) {
    int node = blockIdx.x * 8 + (threadIdx.x >> 5);
    if (node >= NN) return;
    int lane = threadIdx.x & 31;
    int beg = g_rowptr[node], end = g_rowptr[node + 1];
    float adst = g_adst2[node];
    float den = 0.f;
    float2 acc[2];
    acc[0] = make_float2(0.f, 0.f);
    acc[1] = make_float2(0.f, 0.f);
    int i = beg;
    for (; i + 2 <= end; i += 2) {
        int s0 = g_csrc[i], s1 = g_csrc[i + 1];
        float x0 = g_asrc2[s0] + adst;
        x0 = x0 > 0.f ? x0 : 0.2f * x0;
        float w0 = __expf(x0);
        float x1 = g_asrc2[s1] + adst;
        x1 = x1 > 0.f ? x1 : 0.2f * x1;
        float w1 = __expf(x1);
        den += w0 + w1;
        const __half2* h0 = (const __half2*)(g_h2h + (size_t)s0 * 128);
        const __half2* h1p = (const __half2*)(g_h2h + (size_t)s1 * 128);
        __half2 r0[2], r1[2];
#pragma unroll
        for (int j = 0; j < 2; j++) r0[j] = h0[j * 32 + lane];
#pragma unroll
        for (int j = 0; j < 2; j++) r1[j] = h1p[j * 32 + lane];
#pragma unroll
        for (int j = 0; j < 2; j++) {
            float2 f0 = __half22float2(r0[j]);
            float2 f1 = __half22float2(r1[j]);
            acc[j].x += w0 * f0.x + w1 * f1.x;
            acc[j].y += w0 * f0.y + w1 * f1.y;
        }
    }
    if (i < end) {
        int s0 = g_csrc[i];
        float x0 = g_asrc2[s0] + adst;
        x0 = x0 > 0.f ? x0 : 0.2f * x0;
        float w0 = __expf(x0);
        den += w0;
        const __half2* h0 = (const __half2*)(g_h2h + (size_t)s0 * 128);
#pragma unroll
        for (int j = 0; j < 2; j++) {
            float2 f0 = __half22float2(h0[j * 32 + lane]);
            acc[j].x += w0 * f0.x;
            acc[j].y += w0 * f0.y;
        }
    }
    float* od = g_out2 + (size_t)node * 128;
    float inv = 1.f / (den + 1e-16f);
#pragma unroll
    for (int j = 0; j < 2; j++) {
        int c = (j * 32 + lane) * 2;
        float2 bb = *(const float2*)(b2 + c);
        float v0 = acc[j].x * inv + bb.x;
        float v1 = acc[j].y * inv + bb.y;
        v0 = v0 > 0.f ? v0 : expm1f(v0);
        v1 = v1 > 0.f ? v1 : expm1f(v1);
        *(float2*)(od + c) = make_float2(v0, v1);
    }
}

// ---------------- global max pool (parallel, segment flush) ------------------
__global__ void k_pool(const int* __restrict__ batch) {
    int base = blockIdx.x * 128;
    int c = threadIdx.x;  // 128
    int lim = base + 128; if (lim > NN) lim = NN;
    int curg = batch[base];
    float mx = -3.4e38f;
    for (int n = base; n < lim; n++) {
        int g = batch[n];
        if (g != curg) {
            atomicMaxF(&g_pooled[curg * 128 + c], mx);
            curg = g;
            mx = -3.4e38f;
        }
        mx = fmaxf(mx, g_out2[(size_t)n * 128 + c]);
    }
    atomicMaxF(&g_pooled[curg * 128 + c], mx);
}

// ---------------- classifier --------------------------------------------------
__global__ void k_cls(const float* __restrict__ Wc1, const float* __restrict__ bc1,
                      const float* __restrict__ Wc2, const float* __restrict__ bc2,
                      float* __restrict__ out) {
    int g = blockIdx.x;
    int t = threadIdx.x;  // 64
    __shared__ float sp[128];
    __shared__ float sh[64];
    sp[t] = g_pooled[g * 128 + t];
    sp[t + 64] = g_pooled[g * 128 + 64 + t];
    __syncthreads();
    float s = bc1[t];
    for (int k = 0; k < 128; k++) s += sp[k] * Wc1[k * 64 + t];
    sh[t] = fmaxf(s, 0.f);
    __syncthreads();
    if (t < NCLS) {
        float o = bc2[t];
        for (int k = 0; k < 64; k++) o += sh[k] * Wc2[k * NCLS + t];
        out[g * NCLS + t] = o;
    }
}

// ---------------- launch ------------------------------------------------------
extern "C" void kernel_launch(void* const* d_in, const int* in_sizes, int n_in,
                              void* d_out, int out_size) {
    const float* xs    = (const float*)d_in[0];
    const int*   xop   = (const int*)d_in[1];
    const int*   xsrc  = (const int*)d_in[2];
    const int*   xsink = (const int*)d_in[3];
    const int*   xstr  = (const int*)d_in[4];
    const int*   xpay  = (const int*)d_in[5];
    const int*   ei    = (const int*)d_in[6];
    const int*   batch = (const int*)d_in[7];
    const float* eop   = (const float*)d_in[8];
    const float* esrc  = (const float*)d_in[9];
    const float* esink = (const float*)d_in[10];
    const float* estr  = (const float*)d_in[11];
    const float* epay  = (const float*)d_in[12];
    const float* ln_g  = (const float*)d_in[13];
    const float* ln_b  = (const float*)d_in[14];
    const float* W1    = (const float*)d_in[15];
    const float* as1   = (const float*)d_in[16];
    const float* ad1   = (const float*)d_in[17];
    const float* b1    = (const float*)d_in[18];
    const float* W2    = (const float*)d_in[19];
    const float* as2   = (const float*)d_in[20];
    const float* ad2   = (const float*)d_in[21];
    const float* b2    = (const float*)d_in[22];
    const float* Wc1   = (const float*)d_in[23];
    const float* bc1   = (const float*)d_in[24];
    const float* Wc2   = (const float*)d_in[25];
    const float* bc2   = (const float*)d_in[26];
    float* out = (float*)d_out;

    __half *p_featsh, *p_h1h, *p_out1h, *p_h2h;
    cudaGetSymbolAddress((void**)&p_featsh, g_featsh);
    cudaGetSymbolAddress((void**)&p_h1h, g_h1h);
    cudaGetSymbolAddress((void**)&p_out1h, g_out1h);
    cudaGetSymbolAddress((void**)&p_h2h, g_h2h);

    int eb = (ET + 255) / 256;
    int nwb = (NN + 7) / 8;  // warp-per-node blocks (256 thr)

    // fused init (deg zero + pooled init + P1 prep)
    k_init<<<(NN + 255) / 256, 256>>>(W1, as1, ad1);
    // CSR build
    k_deg<<<eb, 256>>>(ei);
    k_scan<<<1, 1024>>>();
    k_fill<<<eb, 256>>>(ei);

    // features (+ fused conv1 logits)
    k_feats<<<NN, 256>>>(xs, xop, xsrc, xsink, xstr, xpay,
                         eop, esrc, esink, estr, epay, ln_g, ln_b);

    // conv1
    {
        dim3 grid(512 / 128, (NN + 127) / 128);
        k_hgemm<<<grid, 256>>>(p_featsh, W1, p_h1h, NN, 512, 256);
    }
    k_agg1<<<nwb, 256>>>(b1);

    // conv2
    {
        dim3 grid(1, (NN + 127) / 128);
        k_hgemm<<<grid, 256>>>(p_out1h, W2, p_h2h, NN, 128, 512);
    }
    k_att2<<<nwb, 256>>>(as2, ad2);
    k_agg2<<<nwb, 256>>>(b2);

    // pool + classify
    k_pool<<<(NN + 127) / 128, 128>>>(batch);
    k_cls<<<GG, 64>>>(Wc1, bc1, Wc2, bc2, out);
}